// round 1
// baseline (speedup 1.0000x reference)
#include <cuda_runtime.h>
#include <math.h>

#define NB 8
#define NP 1024
#define KNN 20

// ---------------- scratch (device globals; no allocation allowed) ----------------
__device__ float g_dist[NB * NP * NP];      // 32 MB pairwise neg-sqdist
__device__ int   g_idx[NB * NP * KNN];      // knn indices
__device__ float g_xx[NB * NP];             // squared norms
__device__ float g_cat[NB * NP * 448];      // concatenated per-point features [B][N][448]
__device__ float g_ab[NB * NP * 1024];      // per-point a/b projections [B][N][2*O], O<=512
__device__ float g_hf[NB * NP * 512];       // final layer per-point output
__device__ float g_pooled[NB * 512];
__device__ float g_wab[1024 * 448];         // folded weights [2*O][C]
__device__ float g_bias[512];

// ---------------- squared norms: one warp per point ----------------
__global__ void xx_kernel(const float* __restrict__ h, int ld, int coff, int C,
                          float* __restrict__ xx)
{
    int warp = (blockIdx.x * blockDim.x + threadIdx.x) >> 5;
    int lane = threadIdx.x & 31;
    if (warp >= NB * NP) return;
    const float* p = h + (size_t)warp * ld + coff;
    float s = 0.f;
    for (int c = lane; c < C; c += 32) { float t = p[c]; s += t * t; }
    #pragma unroll
    for (int o = 16; o; o >>= 1) s += __shfl_xor_sync(0xffffffffu, s, o);
    if (!lane) xx[warp] = s;
}

// ---------------- tiled fp32 GEMM: neg squared distance matrix ----------------
#define BM 64
#define BN 64
#define BKK 16

__global__ void gemm_dist_kernel(const float* __restrict__ h, int ld, int coff, int C,
                                 const float* __restrict__ xx, float* __restrict__ dist)
{
    int b = blockIdx.z;
    int row0 = blockIdx.y * BM;
    int col0 = blockIdx.x * BN;
    __shared__ float As[BKK][BM + 1];
    __shared__ float Bs[BKK][BN + 1];
    int tid = threadIdx.x;
    int tx = tid & 15, ty = tid >> 4;
    const float* base = h + (size_t)b * NP * ld + coff;
    float acc[4][4] = {};
    for (int k0 = 0; k0 < C; k0 += BKK) {
        #pragma unroll
        for (int e = 0; e < 4; e++) {
            int i = ty + e * 16;
            int c = tx;
            float va = 0.f, vb = 0.f;
            if (k0 + c < C) {
                va = base[(size_t)(row0 + i) * ld + k0 + c];
                vb = base[(size_t)(col0 + i) * ld + k0 + c];
            }
            As[c][i] = va;
            Bs[c][i] = vb;
        }
        __syncthreads();
        #pragma unroll
        for (int kk = 0; kk < BKK; kk++) {
            float aF[4], bF[4];
            #pragma unroll
            for (int r = 0; r < 4; r++) aF[r] = As[kk][ty * 4 + r];
            #pragma unroll
            for (int s = 0; s < 4; s++) bF[s] = Bs[kk][tx * 4 + s];
            #pragma unroll
            for (int r = 0; r < 4; r++)
                #pragma unroll
                for (int s = 0; s < 4; s++)
                    acc[r][s] = fmaf(aF[r], bF[s], acc[r][s]);
        }
        __syncthreads();
    }
    const float* xxb = xx + b * NP;
    #pragma unroll
    for (int r = 0; r < 4; r++) {
        int i = row0 + ty * 4 + r;
        float xi = xxb[i];
        #pragma unroll
        for (int s = 0; s < 4; s++) {
            int j = col0 + tx * 4 + s;
            dist[((size_t)b * NP + i) * NP + j] = 2.f * acc[r][s] - xi - xxb[j];
        }
    }
}

// ---------------- tiled fp32 GEMM: folded weight projection ----------------
// outab[b][i][n] = sum_c h[b][i][c] * W[n][c],   n in [0, Ncols)
__global__ void gemm_w_kernel(const float* __restrict__ h, int ld, int coff, int C,
                              const float* __restrict__ W, int Ncols,
                              float* __restrict__ outab)
{
    int b = blockIdx.z;
    int row0 = blockIdx.y * BM;
    int col0 = blockIdx.x * BN;
    __shared__ float As[BKK][BM + 1];
    __shared__ float Bs[BKK][BN + 1];
    int tid = threadIdx.x;
    int tx = tid & 15, ty = tid >> 4;
    const float* base = h + (size_t)b * NP * ld + coff;
    float acc[4][4] = {};
    for (int k0 = 0; k0 < C; k0 += BKK) {
        #pragma unroll
        for (int e = 0; e < 4; e++) {
            int i = ty + e * 16;
            int c = tx;
            float va = 0.f, vb = 0.f;
            if (k0 + c < C) {
                va = base[(size_t)(row0 + i) * ld + k0 + c];
                vb = W[(size_t)(col0 + i) * C + k0 + c];
            }
            As[c][i] = va;
            Bs[c][i] = vb;
        }
        __syncthreads();
        #pragma unroll
        for (int kk = 0; kk < BKK; kk++) {
            float aF[4], bF[4];
            #pragma unroll
            for (int r = 0; r < 4; r++) aF[r] = As[kk][ty * 4 + r];
            #pragma unroll
            for (int s = 0; s < 4; s++) bF[s] = Bs[kk][tx * 4 + s];
            #pragma unroll
            for (int r = 0; r < 4; r++)
                #pragma unroll
                for (int s = 0; s < 4; s++)
                    acc[r][s] = fmaf(aF[r], bF[s], acc[r][s]);
        }
        __syncthreads();
    }
    #pragma unroll
    for (int r = 0; r < 4; r++) {
        int i = row0 + ty * 4 + r;
        #pragma unroll
        for (int s = 0; s < 4; s++) {
            int j = col0 + tx * 4 + s;
            outab[((size_t)b * NP + i) * Ncols + j] = acc[r][s];
        }
    }
}

// ---------------- top-20 selection: one warp per row of 1024 ----------------
__global__ void topk_kernel(const float* __restrict__ dist, int* __restrict__ idx)
{
    int row = blockIdx.x * (blockDim.x >> 5) + (threadIdx.x >> 5);
    int lane = threadIdx.x & 31;
    if (row >= NB * NP) return;
    const float* d = dist + (size_t)row * NP;
    float v[32];
    #pragma unroll
    for (int s = 0; s < 32; s++) v[s] = d[s * 32 + lane];
    for (int t = 0; t < KNN; t++) {
        float best = -3.4e38f; int bs = 0;
        #pragma unroll
        for (int s = 0; s < 32; s++)
            if (v[s] > best) { best = v[s]; bs = s; }
        int bj = bs * 32 + lane;
        #pragma unroll
        for (int off = 16; off; off >>= 1) {
            float ov = __shfl_xor_sync(0xffffffffu, best, off);
            int oj = __shfl_xor_sync(0xffffffffu, bj, off);
            if (ov > best || (ov == best && oj < bj)) { best = ov; bj = oj; }
        }
        if ((bj & 31) == lane) {
            int ks = bj >> 5;
            #pragma unroll
            for (int s = 0; s < 32; s++)
                if (s == ks) v[s] = -3.4e38f;
        }
        if (lane == 0) idx[row * KNN + t] = bj;
    }
}

// ---------------- fold conv weights + BN into (a, b) projection ----------------
// W: [O][2C]; wab rows 0..O-1 = s*(Wd - Wc) (center part -> 'a'),
//             rows O..2O-1     = s*Wc        (neighbor part -> 'b')
__global__ void fold_kernel(const float* __restrict__ W, const float* __restrict__ g,
                            const float* __restrict__ be, const float* __restrict__ m,
                            const float* __restrict__ v, int O, int C,
                            float* __restrict__ wab, float* __restrict__ bias)
{
    int t = blockIdx.x * blockDim.x + threadIdx.x;
    if (t < O * C) {
        int o = t / C, c = t - o * C;
        float s = g[o] / sqrtf(v[o] + 1e-5f);
        float wc = W[o * 2 * C + c];
        float wd = W[o * 2 * C + C + c];
        wab[o * C + c]       = s * (wd - wc);
        wab[(O + o) * C + c] = s * wc;
    }
    if (t < O) bias[t] = be[t] - (g[t] / sqrtf(v[t] + 1e-5f)) * m[t];
}

// ---------------- edge aggregate: mean_k lrelu(a_i + b_idx) ----------------
__global__ void aggregate_kernel(const float* __restrict__ ab, int O,
                                 const float* __restrict__ bias,
                                 const int* __restrict__ idx,
                                 float* __restrict__ out, int ldo, int ooff)
{
    int bi = blockIdx.x;               // 0..8191
    int b = bi >> 10, i = bi & 1023;
    __shared__ int sj[KNN];
    if (threadIdx.x < KNN) sj[threadIdx.x] = idx[bi * KNN + threadIdx.x];
    __syncthreads();
    const float* abb = ab + (size_t)b * NP * 2 * O;
    for (int o = threadIdx.x; o < O; o += blockDim.x) {
        float a = abb[(size_t)i * 2 * O + o] + bias[o];
        float acc = 0.f;
        #pragma unroll
        for (int k = 0; k < KNN; k++) {
            float val = a + abb[(size_t)sj[k] * 2 * O + O + o];
            acc += fmaxf(val, 0.2f * val);
        }
        out[((size_t)b * NP + i) * ldo + ooff + o] = acc * 0.05f;
    }
}

// ---------------- global mean pool over points ----------------
__global__ void pool_kernel(const float* __restrict__ hf, float* __restrict__ pooled)
{
    int b = blockIdx.x;
    int o = blockIdx.y * blockDim.x + threadIdx.x;  // 0..511
    float s = 0.f;
    for (int i = 0; i < NP; i++) s += hf[((size_t)b * NP + i) * 512 + o];
    pooled[b * 512 + o] = s * (1.f / NP);
}

// ---------------- final linear ----------------
__global__ void final_kernel(const float* __restrict__ pooled, const float* __restrict__ We,
                             float* __restrict__ out)
{
    int b = blockIdx.x, e = threadIdx.x;            // 8 x 256
    const float* p = pooled + b * 512;
    const float* w = We + e * 512;
    float s = 0.f;
    for (int o = 0; o < 512; o++) s += p[o] * w[o];
    out[b * 256 + e] = s;
}

// ---------------- host-side layer driver ----------------
static void run_layer(const float* hin, int ld, int coff, int C,
                      const float* W, const float* g, const float* be,
                      const float* m, const float* v, int O,
                      float* outbuf, int ldo, int ooff,
                      float* dist, float* xx, int* idx,
                      float* wab, float* bias, float* ab)
{
    xx_kernel<<<NB * NP / 8, 256>>>(hin, ld, coff, C, xx);
    dim3 gd(NP / BN, NP / BM, NB);
    gemm_dist_kernel<<<gd, 256>>>(hin, ld, coff, C, xx, dist);
    topk_kernel<<<NB * NP / 8, 256>>>(dist, idx);
    int foldT = O * C;
    fold_kernel<<<(foldT + 255) / 256, 256>>>(W, g, be, m, v, O, C, wab, bias);
    dim3 gw((2 * O) / BN, NP / BM, NB);
    gemm_w_kernel<<<gw, 256>>>(hin, ld, coff, C, wab, 2 * O, ab);
    int bt = O < 256 ? O : 256;
    aggregate_kernel<<<NB * NP, bt>>>(ab, O, bias, idx, outbuf, ldo, ooff);
}

extern "C" void kernel_launch(void* const* d_in, const int* in_sizes, int n_in,
                              void* d_out, int out_size)
{
    const float* x  = (const float*)d_in[0];
    const float* W0 = (const float*)d_in[1];
    const float* g0 = (const float*)d_in[2];
    const float* b0 = (const float*)d_in[3];
    const float* m0 = (const float*)d_in[4];
    const float* v0 = (const float*)d_in[5];
    const float* W1 = (const float*)d_in[6];
    const float* g1 = (const float*)d_in[7];
    const float* b1 = (const float*)d_in[8];
    const float* m1 = (const float*)d_in[9];
    const float* v1 = (const float*)d_in[10];
    const float* W2 = (const float*)d_in[11];
    const float* g2 = (const float*)d_in[12];
    const float* b2 = (const float*)d_in[13];
    const float* m2 = (const float*)d_in[14];
    const float* v2 = (const float*)d_in[15];
    const float* Wf = (const float*)d_in[16];
    const float* gf = (const float*)d_in[17];
    const float* bf = (const float*)d_in[18];
    const float* mf = (const float*)d_in[19];
    const float* vf = (const float*)d_in[20];
    const float* We = (const float*)d_in[21];

    float *dist, *xx, *cat, *ab, *hf, *pooled, *wab, *bias;
    int* idx;
    cudaGetSymbolAddress((void**)&dist,   g_dist);
    cudaGetSymbolAddress((void**)&idx,    g_idx);
    cudaGetSymbolAddress((void**)&xx,     g_xx);
    cudaGetSymbolAddress((void**)&cat,    g_cat);
    cudaGetSymbolAddress((void**)&ab,     g_ab);
    cudaGetSymbolAddress((void**)&hf,     g_hf);
    cudaGetSymbolAddress((void**)&pooled, g_pooled);
    cudaGetSymbolAddress((void**)&wab,    g_wab);
    cudaGetSymbolAddress((void**)&bias,   g_bias);

    // layer 0: input x [B][N][3], output -> cat cols [0, 64)
    run_layer(x,   3,   0,   3, W0, g0, b0, m0, v0,  64, cat, 448, 0,
              dist, xx, idx, wab, bias, ab);
    // layer 1: input cat cols [0,64), output -> cat cols [64, 192)
    run_layer(cat, 448, 0,  64, W1, g1, b1, m1, v1, 128, cat, 448, 64,
              dist, xx, idx, wab, bias, ab);
    // layer 2: input cat cols [64,192), output -> cat cols [192, 448)
    run_layer(cat, 448, 64, 128, W2, g2, b2, m2, v2, 256, cat, 448, 192,
              dist, xx, idx, wab, bias, ab);
    // final edge-conv: input full cat [0,448), output -> hf [B][N][512]
    run_layer(cat, 448, 0, 448, Wf, gf, bf, mf, vf, 512, hf, 512, 0,
              dist, xx, idx, wab, bias, ab);

    pool_kernel<<<dim3(NB, 2), 256>>>(hf, pooled);
    final_kernel<<<NB, 256>>>(pooled, We, (float*)d_out);
}

// round 2
// speedup vs baseline: 1.3287x; 1.3287x over previous
#include <cuda_runtime.h>
#include <math.h>

#define NB 8
#define NP 1024
#define KNN 20

// ---------------- scratch (device globals; no allocation allowed) ----------------
__device__ __align__(16) float g_dist[NB * NP * NP];      // 32 MB pairwise neg-sqdist
__device__ __align__(16) int   g_idx[NB * NP * KNN];      // knn indices
__device__ __align__(16) float g_xx[NB * NP];             // squared norms
__device__ __align__(16) float g_cat[NB * NP * 448];      // concatenated per-point features
__device__ __align__(16) float g_ab[NB * NP * 1024];      // per-point a/b projections
__device__ __align__(16) float g_hf[NB * NP * 512];       // final layer per-point output
__device__ __align__(16) float g_pooled[NB * 512];
__device__ __align__(16) float g_wab[1024 * 448];         // folded weights [2*O][C]
__device__ __align__(16) float g_bias[512];

// ---------------- squared norms: one warp per point ----------------
__global__ void xx_kernel(const float* __restrict__ h, int ld, int coff, int C,
                          float* __restrict__ xx)
{
    int warp = (blockIdx.x * blockDim.x + threadIdx.x) >> 5;
    int lane = threadIdx.x & 31;
    if (warp >= NB * NP) return;
    const float* p = h + (size_t)warp * ld + coff;
    float s = 0.f;
    for (int c = lane; c < C; c += 32) { float t = p[c]; s += t * t; }
    #pragma unroll
    for (int o = 16; o; o >>= 1) s += __shfl_xor_sync(0xffffffffu, s, o);
    if (!lane) xx[warp] = s;
}

// =================================================================
// 128x128x16 fp32 GEMM core. 256 threads, 8x8 microtile per thread.
// A: rows of `ha` (ld lda, col offset aoff), B: rows of `hb` (ld ldb, boff).
// Computes acc[r][s] = sum_c A[row][c] * B[col][c].
// MODE 0: dist epilogue (2*acc - xx_i - xx_j). MODE 1: plain store.
// =================================================================
#define TBM 128
#define TBN 128
#define TBK 16

template<int MODE>
__global__ __launch_bounds__(256, 2) void gemm128_kernel(
    const float* __restrict__ ha, int lda, int aoff,
    const float* __restrict__ hb, int ldb, int boff,
    int C, int bstrideA, int bstrideB,
    const float* __restrict__ xx,
    float* __restrict__ out, int ldo)
{
    __shared__ float As[TBK][TBM + 4];
    __shared__ float Bs[TBK][TBN + 4];

    int b = blockIdx.z;
    int row0 = blockIdx.y * TBM;
    int col0 = blockIdx.x * TBN;
    int tid = threadIdx.x;
    int tx = tid & 15, ty = tid >> 4;

    const float* Abase = ha + (size_t)b * bstrideA + aoff;
    const float* Bbase = hb + (size_t)b * bstrideB + boff;

    int lr = tid >> 1;           // 0..127
    int lc = (tid & 1) * 8;      // 0 or 8

    bool vec = ((C & 15) == 0);

    float acc[8][8] = {};

    for (int k0 = 0; k0 < C; k0 += TBK) {
        if (vec) {
            const float* ap = Abase + (size_t)(row0 + lr) * lda + k0 + lc;
            const float* bp = Bbase + (size_t)(col0 + lr) * ldb + k0 + lc;
            float4 a0 = *(const float4*)(ap);
            float4 a1 = *(const float4*)(ap + 4);
            float4 b0 = *(const float4*)(bp);
            float4 b1 = *(const float4*)(bp + 4);
            As[lc + 0][lr] = a0.x; As[lc + 1][lr] = a0.y;
            As[lc + 2][lr] = a0.z; As[lc + 3][lr] = a0.w;
            As[lc + 4][lr] = a1.x; As[lc + 5][lr] = a1.y;
            As[lc + 6][lr] = a1.z; As[lc + 7][lr] = a1.w;
            Bs[lc + 0][lr] = b0.x; Bs[lc + 1][lr] = b0.y;
            Bs[lc + 2][lr] = b0.z; Bs[lc + 3][lr] = b0.w;
            Bs[lc + 4][lr] = b1.x; Bs[lc + 5][lr] = b1.y;
            Bs[lc + 6][lr] = b1.z; Bs[lc + 7][lr] = b1.w;
        } else {
            #pragma unroll
            for (int u = 0; u < 8; u++) {
                int c = k0 + lc + u;
                float va = 0.f, vb = 0.f;
                if (c < C) {
                    va = Abase[(size_t)(row0 + lr) * lda + c];
                    vb = Bbase[(size_t)(col0 + lr) * ldb + c];
                }
                As[lc + u][lr] = va;
                Bs[lc + u][lr] = vb;
            }
        }
        __syncthreads();

        #pragma unroll
        for (int kk = 0; kk < TBK; kk++) {
            float4 af0 = *(const float4*)&As[kk][ty * 8];
            float4 af1 = *(const float4*)&As[kk][ty * 8 + 4];
            float4 bf0 = *(const float4*)&Bs[kk][tx * 8];
            float4 bf1 = *(const float4*)&Bs[kk][tx * 8 + 4];
            float aF[8] = {af0.x, af0.y, af0.z, af0.w, af1.x, af1.y, af1.z, af1.w};
            float bF[8] = {bf0.x, bf0.y, bf0.z, bf0.w, bf1.x, bf1.y, bf1.z, bf1.w};
            #pragma unroll
            for (int r = 0; r < 8; r++)
                #pragma unroll
                for (int s = 0; s < 8; s++)
                    acc[r][s] = fmaf(aF[r], bF[s], acc[r][s]);
        }
        __syncthreads();
    }

    if (MODE == 0) {
        const float* xxb = xx + b * NP;
        float xj[8];
        #pragma unroll
        for (int s = 0; s < 8; s++) xj[s] = xxb[col0 + tx * 8 + s];
        #pragma unroll
        for (int r = 0; r < 8; r++) {
            int i = row0 + ty * 8 + r;
            float xi = xxb[i];
            float4 o0, o1;
            o0.x = 2.f * acc[r][0] - xi - xj[0];
            o0.y = 2.f * acc[r][1] - xi - xj[1];
            o0.z = 2.f * acc[r][2] - xi - xj[2];
            o0.w = 2.f * acc[r][3] - xi - xj[3];
            o1.x = 2.f * acc[r][4] - xi - xj[4];
            o1.y = 2.f * acc[r][5] - xi - xj[5];
            o1.z = 2.f * acc[r][6] - xi - xj[6];
            o1.w = 2.f * acc[r][7] - xi - xj[7];
            float* op = out + ((size_t)b * NP + i) * ldo + col0 + tx * 8;
            *(float4*)(op) = o0;
            *(float4*)(op + 4) = o1;
        }
    } else {
        #pragma unroll
        for (int r = 0; r < 8; r++) {
            int i = row0 + ty * 8 + r;
            float4 o0, o1;
            o0.x = acc[r][0]; o0.y = acc[r][1]; o0.z = acc[r][2]; o0.w = acc[r][3];
            o1.x = acc[r][4]; o1.y = acc[r][5]; o1.z = acc[r][6]; o1.w = acc[r][7];
            float* op = out + ((size_t)b * NP + i) * ldo + col0 + tx * 8;
            *(float4*)(op) = o0;
            *(float4*)(op + 4) = o1;
        }
    }
}

// ---------------- top-20 selection: one warp per row of 1024 ----------------
__global__ void topk_kernel(const float* __restrict__ dist, int* __restrict__ idx)
{
    int row = blockIdx.x * (blockDim.x >> 5) + (threadIdx.x >> 5);
    int lane = threadIdx.x & 31;
    if (row >= NB * NP) return;
    const float* d = dist + (size_t)row * NP;
    float v[32];
    #pragma unroll
    for (int s = 0; s < 32; s++) v[s] = d[s * 32 + lane];
    for (int t = 0; t < KNN; t++) {
        float best = -3.4e38f; int bs = 0;
        #pragma unroll
        for (int s = 0; s < 32; s++)
            if (v[s] > best) { best = v[s]; bs = s; }
        int bj = bs * 32 + lane;
        #pragma unroll
        for (int off = 16; off; off >>= 1) {
            float ov = __shfl_xor_sync(0xffffffffu, best, off);
            int oj = __shfl_xor_sync(0xffffffffu, bj, off);
            if (ov > best || (ov == best && oj < bj)) { best = ov; bj = oj; }
        }
        if ((bj & 31) == lane) {
            int ks = bj >> 5;
            #pragma unroll
            for (int s = 0; s < 32; s++)
                if (s == ks) v[s] = -3.4e38f;
        }
        if (lane == 0) idx[row * KNN + t] = bj;
    }
}

// ---------------- fold conv weights + BN into (a, b) projection ----------------
__global__ void fold_kernel(const float* __restrict__ W, const float* __restrict__ g,
                            const float* __restrict__ be, const float* __restrict__ m,
                            const float* __restrict__ v, int O, int C,
                            float* __restrict__ wab, float* __restrict__ bias)
{
    int t = blockIdx.x * blockDim.x + threadIdx.x;
    if (t < O * C) {
        int o = t / C, c = t - o * C;
        float s = g[o] / sqrtf(v[o] + 1e-5f);
        float wc = W[o * 2 * C + c];
        float wd = W[o * 2 * C + C + c];
        wab[o * C + c]       = s * (wd - wc);
        wab[(O + o) * C + c] = s * wc;
    }
    if (t < O) bias[t] = be[t] - (g[t] / sqrtf(v[t] + 1e-5f)) * m[t];
}

// ---------------- edge aggregate: mean_k lrelu(a_i + b_idx) ----------------
__global__ void aggregate_kernel(const float* __restrict__ ab, int O,
                                 const float* __restrict__ bias,
                                 const int* __restrict__ idx,
                                 float* __restrict__ out, int ldo, int ooff)
{
    int bi = blockIdx.x;               // 0..8191
    int b = bi >> 10, i = bi & 1023;
    __shared__ int sj[KNN];
    if (threadIdx.x < KNN) sj[threadIdx.x] = idx[bi * KNN + threadIdx.x];
    __syncthreads();
    const float* abb = ab + (size_t)b * NP * 2 * O;
    for (int o = threadIdx.x; o < O; o += blockDim.x) {
        float a = abb[(size_t)i * 2 * O + o] + bias[o];
        float acc = 0.f;
        #pragma unroll
        for (int k = 0; k < KNN; k++) {
            float val = a + abb[(size_t)sj[k] * 2 * O + O + o];
            acc += fmaxf(val, 0.2f * val);
        }
        out[((size_t)b * NP + i) * ldo + ooff + o] = acc * 0.05f;
    }
}

// ---------------- global mean pool over points ----------------
__global__ void pool_kernel(const float* __restrict__ hf, float* __restrict__ pooled)
{
    int b = blockIdx.x;
    int o = blockIdx.y * blockDim.x + threadIdx.x;  // 0..511
    float s = 0.f;
    for (int i = 0; i < NP; i++) s += hf[((size_t)b * NP + i) * 512 + o];
    pooled[b * 512 + o] = s * (1.f / NP);
}

// ---------------- final linear ----------------
__global__ void final_kernel(const float* __restrict__ pooled, const float* __restrict__ We,
                             float* __restrict__ out)
{
    int b = blockIdx.x, e = threadIdx.x;            // 8 x 256
    const float* p = pooled + b * 512;
    const float* w = We + e * 512;
    float s = 0.f;
    for (int o = 0; o < 512; o++) s += p[o] * w[o];
    out[b * 256 + e] = s;
}

// ---------------- host-side layer driver ----------------
static void run_layer(const float* hin, int ld, int coff, int C,
                      const float* W, const float* g, const float* be,
                      const float* m, const float* v, int O,
                      float* outbuf, int ldo, int ooff,
                      float* dist, float* xx, int* idx,
                      float* wab, float* bias, float* ab)
{
    xx_kernel<<<NB * NP / 8, 256>>>(hin, ld, coff, C, xx);

    dim3 gd(NP / TBN, NP / TBM, NB);
    gemm128_kernel<0><<<gd, 256>>>(hin, ld, coff, hin, ld, coff, C,
                                   NP * ld, NP * ld, xx, dist, NP);

    topk_kernel<<<NB * NP / 8, 256>>>(dist, idx);

    int foldT = O * C;
    fold_kernel<<<(foldT + 255) / 256, 256>>>(W, g, be, m, v, O, C, wab, bias);

    dim3 gw((2 * O) / TBN, NP / TBM, NB);
    gemm128_kernel<1><<<gw, 256>>>(hin, ld, coff, wab, C, 0, C,
                                   NP * ld, 0, nullptr, ab, 2 * O);

    int bt = O < 256 ? O : 256;
    aggregate_kernel<<<NB * NP, bt>>>(ab, O, bias, idx, outbuf, ldo, ooff);
}

extern "C" void kernel_launch(void* const* d_in, const int* in_sizes, int n_in,
                              void* d_out, int out_size)
{
    const float* x  = (const float*)d_in[0];
    const float* W0 = (const float*)d_in[1];
    const float* g0 = (const float*)d_in[2];
    const float* b0 = (const float*)d_in[3];
    const float* m0 = (const float*)d_in[4];
    const float* v0 = (const float*)d_in[5];
    const float* W1 = (const float*)d_in[6];
    const float* g1 = (const float*)d_in[7];
    const float* b1 = (const float*)d_in[8];
    const float* m1 = (const float*)d_in[9];
    const float* v1 = (const float*)d_in[10];
    const float* W2 = (const float*)d_in[11];
    const float* g2 = (const float*)d_in[12];
    const float* b2 = (const float*)d_in[13];
    const float* m2 = (const float*)d_in[14];
    const float* v2 = (const float*)d_in[15];
    const float* Wf = (const float*)d_in[16];
    const float* gf = (const float*)d_in[17];
    const float* bf = (const float*)d_in[18];
    const float* mf = (const float*)d_in[19];
    const float* vf = (const float*)d_in[20];
    const float* We = (const float*)d_in[21];

    float *dist, *xx, *cat, *ab, *hf, *pooled, *wab, *bias;
    int* idx;
    cudaGetSymbolAddress((void**)&dist,   g_dist);
    cudaGetSymbolAddress((void**)&idx,    g_idx);
    cudaGetSymbolAddress((void**)&xx,     g_xx);
    cudaGetSymbolAddress((void**)&cat,    g_cat);
    cudaGetSymbolAddress((void**)&ab,     g_ab);
    cudaGetSymbolAddress((void**)&hf,     g_hf);
    cudaGetSymbolAddress((void**)&pooled, g_pooled);
    cudaGetSymbolAddress((void**)&wab,    g_wab);
    cudaGetSymbolAddress((void**)&bias,   g_bias);

    // layer 0: input x [B][N][3], output -> cat cols [0, 64)
    run_layer(x,   3,   0,   3, W0, g0, b0, m0, v0,  64, cat, 448, 0,
              dist, xx, idx, wab, bias, ab);
    // layer 1: input cat cols [0,64), output -> cat cols [64, 192)
    run_layer(cat, 448, 0,  64, W1, g1, b1, m1, v1, 128, cat, 448, 64,
              dist, xx, idx, wab, bias, ab);
    // layer 2: input cat cols [64,192), output -> cat cols [192, 448)
    run_layer(cat, 448, 64, 128, W2, g2, b2, m2, v2, 256, cat, 448, 192,
              dist, xx, idx, wab, bias, ab);
    // final edge-conv: input full cat [0,448), output -> hf [B][N][512]
    run_layer(cat, 448, 0, 448, Wf, gf, bf, mf, vf, 512, hf, 512, 0,
              dist, xx, idx, wab, bias, ab);

    pool_kernel<<<dim3(NB, 2), 256>>>(hf, pooled);
    final_kernel<<<NB, 256>>>(pooled, We, (float*)d_out);
}

// round 4
// speedup vs baseline: 1.5497x; 1.1663x over previous
#include <cuda_runtime.h>
#include <cuda_bf16.h>
#include <math.h>
#include <stdint.h>

#define NB 8
#define NP 1024
#define KNN 20
#define KPMAX 1344   // 3*448 rounded to 64

// ---------------- scratch (device globals; no allocation allowed) ----------------
__device__ __align__(16) float g_dist[NB * NP * NP];            // 32 MB
__device__ __align__(16) int   g_idx[NB * NP * KNN];
__device__ __align__(16) float g_xx[NB * NP];
__device__ __align__(16) float g_cat[NB * NP * 448];
__device__ __align__(16) float g_ab[NB * NP * 1024];
__device__ __align__(16) float g_hf[NB * NP * 512];
__device__ __align__(16) float g_pooled[NB * 512];
__device__ __align__(16) float g_wab[1024 * 448];
__device__ __align__(16) float g_bias[512];
__device__ __align__(16) __nv_bfloat16 g_s1[NB * NP * KPMAX];   // [hi|lo|hi]
__device__ __align__(16) __nv_bfloat16 g_s2[NB * NP * KPMAX];   // [hi|hi|lo]
__device__ __align__(16) __nv_bfloat16 g_wabs[1024 * KPMAX];    // weights split [hi|hi|lo]

// =================== squared norms ===================
__global__ void xx_kernel(const float* __restrict__ h, int ld, int coff, int C,
                          float* __restrict__ xx)
{
    int warp = (blockIdx.x * blockDim.x + threadIdx.x) >> 5;
    int lane = threadIdx.x & 31;
    if (warp >= NB * NP) return;
    const float* p = h + (size_t)warp * ld + coff;
    float s = 0.f;
    for (int c = lane; c < C; c += 32) { float t = p[c]; s += t * t; }
    #pragma unroll
    for (int o = 16; o; o >>= 1) s += __shfl_xor_sync(0xffffffffu, s, o);
    if (!lane) xx[warp] = s;
}

// =================== bf16 split conversion ===================
__global__ void split_kernel(const float* __restrict__ src, int ld, int coff, int C,
                             long long bstride, int rows_per_b,
                             __nv_bfloat16* __restrict__ s1,
                             __nv_bfloat16* __restrict__ s2, int Kp)
{
    int r = blockIdx.x;
    int b = r / rows_per_b;
    int ri = r - b * rows_per_b;
    const float* p = src + (long long)b * bstride + (long long)ri * ld + coff;
    __nv_bfloat16* o1 = s1 + (long long)r * Kp;
    __nv_bfloat16* o2 = s2 + (long long)r * Kp;
    __nv_bfloat16 z = __float2bfloat16(0.f);
    for (int k = threadIdx.x; k < Kp; k += blockDim.x) {
        __nv_bfloat16 v1 = z, v2 = z;
        if (k < 3 * C) {
            int region = (k < C) ? 0 : ((k < 2 * C) ? 1 : 2);
            int c = k - region * C;
            float x = p[c];
            __nv_bfloat16 hi = __float2bfloat16(x);
            __nv_bfloat16 lo = __float2bfloat16(x - __bfloat162float(hi));
            v1 = (region == 1) ? lo : hi;
            v2 = (region == 2) ? lo : hi;
        }
        o1[k] = v1;
        o2[k] = v2;
    }
}

// =================== mma.sync bf16 GEMM (128x128x32 tile) ===================
// D[row][col] = sum_k A[row][k] * B[col][k]; A,B K-major bf16, Kp mult of 64.
// mode 0: out = 2*D - xx_i - xx_j. mode 1: plain store.
#define SSTR 56   // smem row stride in elements (112B = 28 banks, 16B-aligned)

__device__ __forceinline__ void mma16816(float* c, const uint32_t* a, const uint32_t* b)
{
    asm volatile(
        "mma.sync.aligned.m16n8k16.row.col.f32.bf16.bf16.f32 "
        "{%0,%1,%2,%3}, {%4,%5,%6,%7}, {%8,%9}, {%0,%1,%2,%3};"
        : "+f"(c[0]), "+f"(c[1]), "+f"(c[2]), "+f"(c[3])
        : "r"(a[0]), "r"(a[1]), "r"(a[2]), "r"(a[3]), "r"(b[0]), "r"(b[1]));
}

__global__ __launch_bounds__(256, 2) void mma_gemm_kernel(
    const __nv_bfloat16* __restrict__ A,
    const __nv_bfloat16* __restrict__ Bm,
    int Kp, long long bsA, long long bsB,
    const float* __restrict__ xx, int mode,
    float* __restrict__ out, int ldo)
{
    __shared__ __align__(16) __nv_bfloat16 As[128 * SSTR];
    __shared__ __align__(16) __nv_bfloat16 Bs[128 * SSTR];

    int b = blockIdx.z;
    int row0 = blockIdx.y * 128;
    int col0 = blockIdx.x * 128;
    int tid = threadIdx.x;
    int wid = tid >> 5, lane = tid & 31;
    int wm = (wid >> 2) * 64;       // warp M origin (0 or 64)
    int wn = (wid & 3) * 32;        // warp N origin (0,32,64,96)

    const __nv_bfloat16* Ab = A + (long long)b * bsA;
    const __nv_bfloat16* Bb = Bm + (long long)b * bsB;

    float acc[4][4][4] = {};

    int lr = tid >> 1;              // 0..127: tile row loaded by this thread
    int lc = (tid & 1) * 16;        // element offset 0 or 16

    for (int k0 = 0; k0 < Kp; k0 += 32) {
        const float4* ga = (const float4*)(Ab + (long long)(row0 + lr) * Kp + k0 + lc);
        const float4* gb = (const float4*)(Bb + (long long)(col0 + lr) * Kp + k0 + lc);
        float4 av0 = ga[0], av1 = ga[1];
        float4 bv0 = gb[0], bv1 = gb[1];
        *(float4*)&As[lr * SSTR + lc]     = av0;
        *(float4*)&As[lr * SSTR + lc + 8] = av1;
        *(float4*)&Bs[lr * SSTR + lc]     = bv0;
        *(float4*)&Bs[lr * SSTR + lc + 8] = bv1;
        __syncthreads();

        int ar = lane >> 2;
        #pragma unroll
        for (int kk = 0; kk < 32; kk += 16) {
            int ac = kk + (lane & 3) * 2;
            uint32_t af[4][4], bf[4][2];
            #pragma unroll
            for (int mf = 0; mf < 4; mf++) {
                const __nv_bfloat16* pa = &As[(wm + mf * 16 + ar) * SSTR + ac];
                af[mf][0] = *(const uint32_t*)(pa);
                af[mf][1] = *(const uint32_t*)(pa + 8 * SSTR);
                af[mf][2] = *(const uint32_t*)(pa + 8);
                af[mf][3] = *(const uint32_t*)(pa + 8 * SSTR + 8);
            }
            #pragma unroll
            for (int nf = 0; nf < 4; nf++) {
                const __nv_bfloat16* pb = &Bs[(wn + nf * 8 + ar) * SSTR + ac];
                bf[nf][0] = *(const uint32_t*)(pb);
                bf[nf][1] = *(const uint32_t*)(pb + 8);
            }
            #pragma unroll
            for (int mf = 0; mf < 4; mf++)
                #pragma unroll
                for (int nf = 0; nf < 4; nf++)
                    mma16816(acc[mf][nf], af[mf], bf[nf]);
        }
        __syncthreads();
    }

    // -------- epilogue --------
    int ar = lane >> 2, ac = (lane & 3) * 2;
    const float* xxb = (mode == 0) ? (xx + b * NP) : nullptr;
    #pragma unroll
    for (int mf = 0; mf < 4; mf++) {
        int r0g = row0 + wm + mf * 16 + ar;
        #pragma unroll
        for (int nf = 0; nf < 4; nf++) {
            int cg = col0 + wn + nf * 8 + ac;
            float* acc4 = acc[mf][nf];
            if (mode == 0) {
                float xj0 = xxb[cg], xj1 = xxb[cg + 1];
                float xi0 = xxb[r0g], xi1 = xxb[r0g + 8];
                float2 v0, v1;
                v0.x = 2.f * acc4[0] - xi0 - xj0;
                v0.y = 2.f * acc4[1] - xi0 - xj1;
                v1.x = 2.f * acc4[2] - xi1 - xj0;
                v1.y = 2.f * acc4[3] - xi1 - xj1;
                *(float2*)(out + ((long long)b * NP + r0g) * ldo + cg) = v0;
                *(float2*)(out + ((long long)b * NP + r0g + 8) * ldo + cg) = v1;
            } else {
                float2 v0, v1;
                v0.x = acc4[0]; v0.y = acc4[1];
                v1.x = acc4[2]; v1.y = acc4[3];
                *(float2*)(out + ((long long)b * NP + r0g) * ldo + cg) = v0;
                *(float2*)(out + ((long long)b * NP + r0g + 8) * ldo + cg) = v1;
            }
        }
    }
}

// =================== top-20 selection ===================
__global__ void topk_kernel(const float* __restrict__ dist, int* __restrict__ idx)
{
    int row = blockIdx.x * (blockDim.x >> 5) + (threadIdx.x >> 5);
    int lane = threadIdx.x & 31;
    if (row >= NB * NP) return;
    const float* d = dist + (size_t)row * NP;
    float v[32];
    #pragma unroll
    for (int s = 0; s < 32; s++) v[s] = d[s * 32 + lane];
    for (int t = 0; t < KNN; t++) {
        float best = -3.4e38f; int bs = 0;
        #pragma unroll
        for (int s = 0; s < 32; s++)
            if (v[s] > best) { best = v[s]; bs = s; }
        int bj = bs * 32 + lane;
        #pragma unroll
        for (int off = 16; off; off >>= 1) {
            float ov = __shfl_xor_sync(0xffffffffu, best, off);
            int oj = __shfl_xor_sync(0xffffffffu, bj, off);
            if (ov > best || (ov == best && oj < bj)) { best = ov; bj = oj; }
        }
        if ((bj & 31) == lane) {
            int ks = bj >> 5;
            #pragma unroll
            for (int s = 0; s < 32; s++)
                if (s == ks) v[s] = -3.4e38f;
        }
        if (lane == 0) idx[row * KNN + t] = bj;
    }
}

// =================== fold conv weights + BN ===================
__global__ void fold_kernel(const float* __restrict__ W, const float* __restrict__ g,
                            const float* __restrict__ be, const float* __restrict__ m,
                            const float* __restrict__ v, int O, int C,
                            float* __restrict__ wab, float* __restrict__ bias)
{
    int t = blockIdx.x * blockDim.x + threadIdx.x;
    if (t < O * C) {
        int o = t / C, c = t - o * C;
        float s = g[o] / sqrtf(v[o] + 1e-5f);
        float wc = W[o * 2 * C + c];
        float wd = W[o * 2 * C + C + c];
        wab[o * C + c]       = s * (wd - wc);
        wab[(O + o) * C + c] = s * wc;
    }
    if (t < O) bias[t] = be[t] - (g[t] / sqrtf(v[t] + 1e-5f)) * m[t];
}

// =================== edge aggregate ===================
__global__ void aggregate_kernel(const float* __restrict__ ab, int O,
                                 const float* __restrict__ bias,
                                 const int* __restrict__ idx,
                                 float* __restrict__ out, int ldo, int ooff)
{
    int bi = blockIdx.x;
    int b = bi >> 10, i = bi & 1023;
    __shared__ int sj[KNN];
    if (threadIdx.x < KNN) sj[threadIdx.x] = idx[bi * KNN + threadIdx.x];
    __syncthreads();
    const float* abb = ab + (size_t)b * NP * 2 * O;
    for (int o = threadIdx.x; o < O; o += blockDim.x) {
        float a = abb[(size_t)i * 2 * O + o] + bias[o];
        float acc = 0.f;
        #pragma unroll
        for (int k = 0; k < KNN; k++) {
            float val = a + abb[(size_t)sj[k] * 2 * O + O + o];
            acc += fmaxf(val, 0.2f * val);
        }
        out[((size_t)b * NP + i) * ldo + ooff + o] = acc * 0.05f;
    }
}

// =================== pooling + final linear ===================
__global__ void pool_kernel(const float* __restrict__ hf, float* __restrict__ pooled)
{
    int b = blockIdx.x;
    int o = blockIdx.y * blockDim.x + threadIdx.x;
    float s = 0.f;
    for (int i = 0; i < NP; i++) s += hf[((size_t)b * NP + i) * 512 + o];
    pooled[b * 512 + o] = s * (1.f / NP);
}

__global__ void final_kernel(const float* __restrict__ pooled, const float* __restrict__ We,
                             float* __restrict__ out)
{
    int b = blockIdx.x, e = threadIdx.x;
    const float* p = pooled + b * 512;
    const float* w = We + e * 512;
    float s = 0.f;
    for (int o = 0; o < 512; o++) s += p[o] * w[o];
    out[b * 256 + e] = s;
}

// =================== host-side layer driver ===================
static void run_layer(const float* hin, int ld, int coff, int C,
                      const float* W, const float* g, const float* be,
                      const float* m, const float* v, int O,
                      float* outbuf, int ldo, int ooff,
                      float* dist, float* xx, int* idx,
                      float* wab, float* bias, float* ab,
                      __nv_bfloat16* s1, __nv_bfloat16* s2, __nv_bfloat16* wabs)
{
    int Kp = ((3 * C + 63) / 64) * 64;

    xx_kernel<<<NB * NP / 8, 256>>>(hin, ld, coff, C, xx);
    split_kernel<<<NB * NP, 128>>>(hin, ld, coff, C, (long long)NP * ld, NP, s1, s2, Kp);

    dim3 gd(NP / 128, NP / 128, NB);
    mma_gemm_kernel<<<gd, 256>>>(s1, s2, Kp, (long long)NP * Kp, (long long)NP * Kp,
                                 xx, 0, dist, NP);

    topk_kernel<<<NB * NP / 8, 256>>>(dist, idx);

    fold_kernel<<<(O * C + 255) / 256, 256>>>(W, g, be, m, v, O, C, wab, bias);
    split_kernel<<<2 * O, 128>>>(wab, C, 0, C, 0, 2 * O, wabs, wabs, Kp);

    dim3 gw((2 * O) / 128, NP / 128, NB);
    mma_gemm_kernel<<<gw, 256>>>(s1, wabs, Kp, (long long)NP * Kp, 0,
                                 nullptr, 1, ab, 2 * O);

    int bt = O < 256 ? O : 256;
    aggregate_kernel<<<NB * NP, bt>>>(ab, O, bias, idx, outbuf, ldo, ooff);
}

extern "C" void kernel_launch(void* const* d_in, const int* in_sizes, int n_in,
                              void* d_out, int out_size)
{
    const float* x  = (const float*)d_in[0];
    const float* W0 = (const float*)d_in[1];
    const float* g0 = (const float*)d_in[2];
    const float* b0 = (const float*)d_in[3];
    const float* m0 = (const float*)d_in[4];
    const float* v0 = (const float*)d_in[5];
    const float* W1 = (const float*)d_in[6];
    const float* g1 = (const float*)d_in[7];
    const float* b1 = (const float*)d_in[8];
    const float* m1 = (const float*)d_in[9];
    const float* v1 = (const float*)d_in[10];
    const float* W2 = (const float*)d_in[11];
    const float* g2 = (const float*)d_in[12];
    const float* b2 = (const float*)d_in[13];
    const float* m2 = (const float*)d_in[14];
    const float* v2 = (const float*)d_in[15];
    const float* Wf = (const float*)d_in[16];
    const float* gf = (const float*)d_in[17];
    const float* bf = (const float*)d_in[18];
    const float* mf = (const float*)d_in[19];
    const float* vf = (const float*)d_in[20];
    const float* We = (const float*)d_in[21];

    float *dist, *xx, *cat, *ab, *hf, *pooled, *wab, *bias;
    int* idx;
    __nv_bfloat16 *s1, *s2, *wabs;
    cudaGetSymbolAddress((void**)&dist,   g_dist);
    cudaGetSymbolAddress((void**)&idx,    g_idx);
    cudaGetSymbolAddress((void**)&xx,     g_xx);
    cudaGetSymbolAddress((void**)&cat,    g_cat);
    cudaGetSymbolAddress((void**)&ab,     g_ab);
    cudaGetSymbolAddress((void**)&hf,     g_hf);
    cudaGetSymbolAddress((void**)&pooled, g_pooled);
    cudaGetSymbolAddress((void**)&wab,    g_wab);
    cudaGetSymbolAddress((void**)&bias,   g_bias);
    cudaGetSymbolAddress((void**)&s1,     g_s1);
    cudaGetSymbolAddress((void**)&s2,     g_s2);
    cudaGetSymbolAddress((void**)&wabs,   g_wabs);

    run_layer(x,   3,   0,   3, W0, g0, b0, m0, v0,  64, cat, 448, 0,
              dist, xx, idx, wab, bias, ab, s1, s2, wabs);
    run_layer(cat, 448, 0,  64, W1, g1, b1, m1, v1, 128, cat, 448, 64,
              dist, xx, idx, wab, bias, ab, s1, s2, wabs);
    run_layer(cat, 448, 64, 128, W2, g2, b2, m2, v2, 256, cat, 448, 192,
              dist, xx, idx, wab, bias, ab, s1, s2, wabs);
    run_layer(cat, 448, 0, 448, Wf, gf, bf, mf, vf, 512, hf, 512, 0,
              dist, xx, idx, wab, bias, ab, s1, s2, wabs);

    pool_kernel<<<dim3(NB, 2), 256>>>(hf, pooled);
    final_kernel<<<NB, 256>>>(pooled, We, (float*)d_out);
}

// round 5
// speedup vs baseline: 1.5684x; 1.0121x over previous
#include <cuda_runtime.h>
#include <cuda_bf16.h>
#include <math.h>
#include <float.h>
#include <stdint.h>

#define NB 8
#define NP 1024
#define KNN 20
#define KPMAX 1344   // 3*448 rounded to 64

// ---------------- scratch (device globals; no allocation allowed) ----------------
__device__ __align__(16) float g_dist[NB * NP * NP];            // 32 MB
__device__ __align__(16) int   g_idx[NB * NP * KNN];
__device__ __align__(16) float g_xx[NB * NP];
__device__ __align__(16) float g_cat[NB * NP * 448];
__device__ __align__(16) float g_ab[NB * NP * 1024];
__device__ __align__(16) float g_hf[NB * NP * 512];
__device__ __align__(16) float g_pooled[NB * 512];
__device__ __align__(16) float g_wab[1024 * 448];
__device__ __align__(16) float g_bias[512];
__device__ __align__(16) __nv_bfloat16 g_s1[NB * NP * KPMAX];   // [hi|lo|hi]
__device__ __align__(16) __nv_bfloat16 g_s2[NB * NP * KPMAX];   // [hi|hi|lo]
__device__ __align__(16) __nv_bfloat16 g_wabs[1024 * KPMAX];    // weights split [hi|hi|lo]

// =================== helpers ===================
__device__ __forceinline__ uint32_t smem_u32(const void* p) {
    uint32_t a;
    asm("{ .reg .u64 t; cvta.to.shared.u64 t, %1; cvt.u32.u64 %0, t; }" : "=r"(a) : "l"(p));
    return a;
}
__device__ __forceinline__ void cpa16(uint32_t s, const void* g) {
    asm volatile("cp.async.cg.shared.global [%0], [%1], 16;" :: "r"(s), "l"(g));
}
#define CP_COMMIT() asm volatile("cp.async.commit_group;")
#define CP_WAIT1()  asm volatile("cp.async.wait_group 1;")
#define CP_WAIT0()  asm volatile("cp.async.wait_group 0;")

// =================== bf16 split + fused squared norms ===================
// s1 = [hi | lo | hi], s2 = [hi | hi | lo], zero-padded to Kp.
// If s1 == s2 (weights), later s2 write wins -> [hi | hi | lo].
// If xxout != null, also writes xx[r] = sum_c x[c]^2 (block reduction).
__global__ void split_kernel(const float* __restrict__ src, int ld, int coff, int C,
                             long long bstride, int rows_per_b,
                             __nv_bfloat16* __restrict__ s1,
                             __nv_bfloat16* __restrict__ s2, int Kp,
                             float* __restrict__ xxout)
{
    __shared__ float red[4];
    int r = blockIdx.x;
    int b = r / rows_per_b;
    int ri = r - b * rows_per_b;
    const float* p = src + (long long)b * bstride + (long long)ri * ld + coff;
    __nv_bfloat16* o1 = s1 + (long long)r * Kp;
    __nv_bfloat16* o2 = s2 + (long long)r * Kp;
    __nv_bfloat16 z = __float2bfloat16(0.f);
    float ss = 0.f;
    for (int k = threadIdx.x; k < Kp; k += blockDim.x) {
        __nv_bfloat16 v1 = z, v2 = z;
        if (k < 3 * C) {
            int region = (k < C) ? 0 : ((k < 2 * C) ? 1 : 2);
            int c = k - region * C;
            float x = p[c];
            if (region == 0) ss += x * x;
            __nv_bfloat16 hi = __float2bfloat16(x);
            __nv_bfloat16 lo = __float2bfloat16(x - __bfloat162float(hi));
            v1 = (region == 1) ? lo : hi;
            v2 = (region == 2) ? lo : hi;
        }
        o1[k] = v1;
        o2[k] = v2;
    }
    if (xxout) {
        int lane = threadIdx.x & 31, w = threadIdx.x >> 5;
        #pragma unroll
        for (int o = 16; o; o >>= 1) ss += __shfl_xor_sync(0xffffffffu, ss, o);
        if (!lane) red[w] = ss;
        __syncthreads();
        if (threadIdx.x == 0)
            xxout[r] = red[0] + red[1] + red[2] + red[3];
    }
}

// =================== mma.sync bf16 GEMM, cp.async double-buffered ===================
// D[row][col] = sum_k A[row][k] * B[col][k]; A,B K-major bf16, Kp mult of 32.
// mode 0: out = 2*D - xx_i - xx_j. mode 1: plain store.
#define SSTR 56          // smem row stride (112B): conflict-free frag loads
#define ASZ  (128 * SSTR)
#define GEMM_SMEM (4 * ASZ * 2)   // 2 stages x (As+Bs) bf16 = 57344 B

__device__ __forceinline__ void mma16816(float* c, const uint32_t* a, const uint32_t* b)
{
    asm volatile(
        "mma.sync.aligned.m16n8k16.row.col.f32.bf16.bf16.f32 "
        "{%0,%1,%2,%3}, {%4,%5,%6,%7}, {%8,%9}, {%0,%1,%2,%3};"
        : "+f"(c[0]), "+f"(c[1]), "+f"(c[2]), "+f"(c[3])
        : "r"(a[0]), "r"(a[1]), "r"(a[2]), "r"(a[3]), "r"(b[0]), "r"(b[1]));
}

__global__ __launch_bounds__(256, 2) void mma_gemm_kernel(
    const __nv_bfloat16* __restrict__ A,
    const __nv_bfloat16* __restrict__ Bm,
    int Kp, long long bsA, long long bsB,
    const float* __restrict__ xx, int mode,
    float* __restrict__ out, int ldo)
{
    extern __shared__ __align__(16) __nv_bfloat16 sm[];
    __nv_bfloat16* As = sm;             // [2][ASZ]
    __nv_bfloat16* Bs = sm + 2 * ASZ;   // [2][ASZ]

    int b = blockIdx.z;
    int row0 = blockIdx.y * 128;
    int col0 = blockIdx.x * 128;
    int tid = threadIdx.x;
    int wid = tid >> 5, lane = tid & 31;
    int wm = (wid >> 2) * 64;
    int wn = (wid & 3) * 32;

    const __nv_bfloat16* Ab = A + (long long)b * bsA;
    const __nv_bfloat16* Bb = Bm + (long long)b * bsB;

    int lr = tid >> 1;            // tile row this thread loads
    int lc = (tid & 1) * 16;      // element offset 0 or 16

    uint32_t sA0 = smem_u32(As) + (uint32_t)(lr * SSTR + lc) * 2;
    uint32_t sB0 = smem_u32(Bs) + (uint32_t)(lr * SSTR + lc) * 2;
    const __nv_bfloat16* gA = Ab + (long long)(row0 + lr) * Kp + lc;
    const __nv_bfloat16* gB = Bb + (long long)(col0 + lr) * Kp + lc;

    int nk = Kp >> 5;

    // prologue: stage 0
    cpa16(sA0, gA); cpa16(sA0 + 16, gA + 8);
    cpa16(sB0, gB); cpa16(sB0 + 16, gB + 8);
    CP_COMMIT();

    float acc[4][4][4] = {};
    int ar = lane >> 2;

    for (int kc = 0; kc < nk; kc++) {
        int cur = kc & 1;
        if (kc + 1 < nk) {
            int nxt = cur ^ 1;
            const __nv_bfloat16* ga = gA + (kc + 1) * 32;
            const __nv_bfloat16* gb = gB + (kc + 1) * 32;
            uint32_t da = sA0 + (uint32_t)(nxt * ASZ) * 2;
            uint32_t db = sB0 + (uint32_t)(nxt * ASZ) * 2;
            cpa16(da, ga); cpa16(da + 16, ga + 8);
            cpa16(db, gb); cpa16(db + 16, gb + 8);
            CP_COMMIT();
            CP_WAIT1();
        } else {
            CP_WAIT0();
        }
        __syncthreads();

        const __nv_bfloat16* Asc = As + cur * ASZ;
        const __nv_bfloat16* Bsc = Bs + cur * ASZ;
        #pragma unroll
        for (int kk = 0; kk < 32; kk += 16) {
            int ac = kk + (lane & 3) * 2;
            uint32_t af[4][4], bf[4][2];
            #pragma unroll
            for (int mf = 0; mf < 4; mf++) {
                const __nv_bfloat16* pa = &Asc[(wm + mf * 16 + ar) * SSTR + ac];
                af[mf][0] = *(const uint32_t*)(pa);
                af[mf][1] = *(const uint32_t*)(pa + 8 * SSTR);
                af[mf][2] = *(const uint32_t*)(pa + 8);
                af[mf][3] = *(const uint32_t*)(pa + 8 * SSTR + 8);
            }
            #pragma unroll
            for (int nf = 0; nf < 4; nf++) {
                const __nv_bfloat16* pb = &Bsc[(wn + nf * 8 + ar) * SSTR + ac];
                bf[nf][0] = *(const uint32_t*)(pb);
                bf[nf][1] = *(const uint32_t*)(pb + 8);
            }
            #pragma unroll
            for (int mf = 0; mf < 4; mf++)
                #pragma unroll
                for (int nf = 0; nf < 4; nf++)
                    mma16816(acc[mf][nf], af[mf], bf[nf]);
        }
        __syncthreads();
    }

    // -------- epilogue --------
    int ac = (lane & 3) * 2;
    const float* xxb = (mode == 0) ? (xx + b * NP) : nullptr;
    #pragma unroll
    for (int mf = 0; mf < 4; mf++) {
        int r0g = row0 + wm + mf * 16 + ar;
        #pragma unroll
        for (int nf = 0; nf < 4; nf++) {
            int cg = col0 + wn + nf * 8 + ac;
            float* acc4 = acc[mf][nf];
            if (mode == 0) {
                float xj0 = xxb[cg], xj1 = xxb[cg + 1];
                float xi0 = xxb[r0g], xi1 = xxb[r0g + 8];
                float2 v0, v1;
                v0.x = 2.f * acc4[0] - xi0 - xj0;
                v0.y = 2.f * acc4[1] - xi0 - xj1;
                v1.x = 2.f * acc4[2] - xi1 - xj0;
                v1.y = 2.f * acc4[3] - xi1 - xj1;
                *(float2*)(out + ((long long)b * NP + r0g) * ldo + cg) = v0;
                *(float2*)(out + ((long long)b * NP + r0g + 8) * ldo + cg) = v1;
            } else {
                float2 v0, v1;
                v0.x = acc4[0]; v0.y = acc4[1];
                v1.x = acc4[2]; v1.y = acc4[3];
                *(float2*)(out + ((long long)b * NP + r0g) * ldo + cg) = v0;
                *(float2*)(out + ((long long)b * NP + r0g + 8) * ldo + cg) = v1;
            }
        }
    }
}

// =================== top-20 selection (cached lane-max) ===================
__global__ void topk_kernel(const float* __restrict__ dist, int* __restrict__ idx)
{
    int row = blockIdx.x * (blockDim.x >> 5) + (threadIdx.x >> 5);
    int lane = threadIdx.x & 31;
    if (row >= NB * NP) return;
    const float* d = dist + (size_t)row * NP;
    float v[32];
    #pragma unroll
    for (int s = 0; s < 32; s++) v[s] = d[s * 32 + lane];

    // per-lane cached max
    float lm = -FLT_MAX; int ls = 0;
    #pragma unroll
    for (int s = 0; s < 32; s++)
        if (v[s] > lm) { lm = v[s]; ls = s; }

    for (int t = 0; t < KNN; t++) {
        float best = lm; int bj = ls * 32 + lane;
        #pragma unroll
        for (int off = 16; off; off >>= 1) {
            float ov = __shfl_xor_sync(0xffffffffu, best, off);
            int oj = __shfl_xor_sync(0xffffffffu, bj, off);
            if (ov > best || (ov == best && oj < bj)) { best = ov; bj = oj; }
        }
        if (lane == 0) idx[row * KNN + t] = bj;
        if ((bj & 31) == lane) {       // only winning lane rescans
            int ks = bj >> 5;
            lm = -FLT_MAX; ls = 0;
            #pragma unroll
            for (int s = 0; s < 32; s++) {
                if (s == ks) v[s] = -FLT_MAX;
                if (v[s] > lm) { lm = v[s]; ls = s; }
            }
        }
    }
}

// =================== fold conv weights + BN ===================
__global__ void fold_kernel(const float* __restrict__ W, const float* __restrict__ g,
                            const float* __restrict__ be, const float* __restrict__ m,
                            const float* __restrict__ v, int O, int C,
                            float* __restrict__ wab, float* __restrict__ bias)
{
    int t = blockIdx.x * blockDim.x + threadIdx.x;
    if (t < O * C) {
        int o = t / C, c = t - o * C;
        float s = g[o] / sqrtf(v[o] + 1e-5f);
        float wc = W[o * 2 * C + c];
        float wd = W[o * 2 * C + C + c];
        wab[o * C + c]       = s * (wd - wc);
        wab[(O + o) * C + c] = s * wc;
    }
    if (t < O) bias[t] = be[t] - (g[t] / sqrtf(v[t] + 1e-5f)) * m[t];
}

// =================== edge aggregate ===================
__global__ void aggregate_kernel(const float* __restrict__ ab, int O,
                                 const float* __restrict__ bias,
                                 const int* __restrict__ idx,
                                 float* __restrict__ out, int ldo, int ooff)
{
    int bi = blockIdx.x;
    int b = bi >> 10, i = bi & 1023;
    __shared__ int sj[KNN];
    if (threadIdx.x < KNN) sj[threadIdx.x] = idx[bi * KNN + threadIdx.x];
    __syncthreads();
    const float* abb = ab + (size_t)b * NP * 2 * O;
    for (int o = threadIdx.x; o < O; o += blockDim.x) {
        float a = abb[(size_t)i * 2 * O + o] + bias[o];
        float acc = 0.f;
        #pragma unroll
        for (int k = 0; k < KNN; k++) {
            float val = a + abb[(size_t)sj[k] * 2 * O + O + o];
            acc += fmaxf(val, 0.2f * val);
        }
        out[((size_t)b * NP + i) * ldo + ooff + o] = acc * 0.05f;
    }
}

// =================== pooling + final linear ===================
__global__ void pool_kernel(const float* __restrict__ hf, float* __restrict__ pooled)
{
    int b = blockIdx.x;
    int o = blockIdx.y * blockDim.x + threadIdx.x;
    float s = 0.f;
    for (int i = 0; i < NP; i++) s += hf[((size_t)b * NP + i) * 512 + o];
    pooled[b * 512 + o] = s * (1.f / NP);
}

__global__ void final_kernel(const float* __restrict__ pooled, const float* __restrict__ We,
                             float* __restrict__ out)
{
    int b = blockIdx.x, e = threadIdx.x;
    const float* p = pooled + b * 512;
    const float* w = We + e * 512;
    float s = 0.f;
    for (int o = 0; o < 512; o++) s += p[o] * w[o];
    out[b * 256 + e] = s;
}

// =================== host-side layer driver ===================
static void run_layer(const float* hin, int ld, int coff, int C,
                      const float* W, const float* g, const float* be,
                      const float* m, const float* v, int O,
                      float* outbuf, int ldo, int ooff,
                      float* dist, float* xx, int* idx,
                      float* wab, float* bias, float* ab,
                      __nv_bfloat16* s1, __nv_bfloat16* s2, __nv_bfloat16* wabs)
{
    int Kp = ((3 * C + 63) / 64) * 64;

    split_kernel<<<NB * NP, 128>>>(hin, ld, coff, C, (long long)NP * ld, NP,
                                   s1, s2, Kp, xx);

    dim3 gd(NP / 128, NP / 128, NB);
    mma_gemm_kernel<<<gd, 256, GEMM_SMEM>>>(s1, s2, Kp,
                                            (long long)NP * Kp, (long long)NP * Kp,
                                            xx, 0, dist, NP);

    topk_kernel<<<NB * NP / 8, 256>>>(dist, idx);

    fold_kernel<<<(O * C + 255) / 256, 256>>>(W, g, be, m, v, O, C, wab, bias);
    split_kernel<<<2 * O, 128>>>(wab, C, 0, C, 0, 2 * O, wabs, wabs, Kp, nullptr);

    dim3 gw((2 * O) / 128, NP / 128, NB);
    mma_gemm_kernel<<<gw, 256, GEMM_SMEM>>>(s1, wabs, Kp, (long long)NP * Kp, 0,
                                            nullptr, 1, ab, 2 * O);

    int bt = O < 256 ? O : 256;
    aggregate_kernel<<<NB * NP, bt>>>(ab, O, bias, idx, outbuf, ldo, ooff);
}

extern "C" void kernel_launch(void* const* d_in, const int* in_sizes, int n_in,
                              void* d_out, int out_size)
{
    const float* x  = (const float*)d_in[0];
    const float* W0 = (const float*)d_in[1];
    const float* g0 = (const float*)d_in[2];
    const float* b0 = (const float*)d_in[3];
    const float* m0 = (const float*)d_in[4];
    const float* v0 = (const float*)d_in[5];
    const float* W1 = (const float*)d_in[6];
    const float* g1 = (const float*)d_in[7];
    const float* b1 = (const float*)d_in[8];
    const float* m1 = (const float*)d_in[9];
    const float* v1 = (const float*)d_in[10];
    const float* W2 = (const float*)d_in[11];
    const float* g2 = (const float*)d_in[12];
    const float* b2 = (const float*)d_in[13];
    const float* m2 = (const float*)d_in[14];
    const float* v2 = (const float*)d_in[15];
    const float* Wf = (const float*)d_in[16];
    const float* gf = (const float*)d_in[17];
    const float* bf = (const float*)d_in[18];
    const float* mf = (const float*)d_in[19];
    const float* vf = (const float*)d_in[20];
    const float* We = (const float*)d_in[21];

    float *dist, *xx, *cat, *ab, *hf, *pooled, *wab, *bias;
    int* idx;
    __nv_bfloat16 *s1, *s2, *wabs;
    cudaGetSymbolAddress((void**)&dist,   g_dist);
    cudaGetSymbolAddress((void**)&idx,    g_idx);
    cudaGetSymbolAddress((void**)&xx,     g_xx);
    cudaGetSymbolAddress((void**)&cat,    g_cat);
    cudaGetSymbolAddress((void**)&ab,     g_ab);
    cudaGetSymbolAddress((void**)&hf,     g_hf);
    cudaGetSymbolAddress((void**)&pooled, g_pooled);
    cudaGetSymbolAddress((void**)&wab,    g_wab);
    cudaGetSymbolAddress((void**)&bias,   g_bias);
    cudaGetSymbolAddress((void**)&s1,     g_s1);
    cudaGetSymbolAddress((void**)&s2,     g_s2);
    cudaGetSymbolAddress((void**)&wabs,   g_wabs);

    cudaFuncSetAttribute(mma_gemm_kernel,
                         cudaFuncAttributeMaxDynamicSharedMemorySize, GEMM_SMEM);

    run_layer(x,   3,   0,   3, W0, g0, b0, m0, v0,  64, cat, 448, 0,
              dist, xx, idx, wab, bias, ab, s1, s2, wabs);
    run_layer(cat, 448, 0,  64, W1, g1, b1, m1, v1, 128, cat, 448, 64,
              dist, xx, idx, wab, bias, ab, s1, s2, wabs);
    run_layer(cat, 448, 64, 128, W2, g2, b2, m2, v2, 256, cat, 448, 192,
              dist, xx, idx, wab, bias, ab, s1, s2, wabs);
    run_layer(cat, 448, 0, 448, Wf, gf, bf, mf, vf, 512, hf, 512, 0,
              dist, xx, idx, wab, bias, ab, s1, s2, wabs);

    pool_kernel<<<dim3(NB, 2), 256>>>(hf, pooled);
    final_kernel<<<NB, 256>>>(pooled, We, (float*)d_out);
}

// round 6
// speedup vs baseline: 1.5887x; 1.0129x over previous
#include <cuda_runtime.h>
#include <cuda_bf16.h>
#include <math.h>
#include <float.h>
#include <stdint.h>

#define NB 8
#define NP 1024
#define KNN 20
#define KPMAX 1344   // 3*448 rounded to 64

// ---------------- scratch (device globals; no allocation allowed) ----------------
__device__ __align__(16) float g_dist[NB * NP * NP];            // 32 MB
__device__ __align__(16) int   g_idx[NB * NP * KNN];
__device__ __align__(16) float g_xx[NB * NP];
__device__ __align__(16) float g_cat[NB * NP * 448];
__device__ __align__(16) float g_ab[NB * NP * 1024];
__device__ __align__(16) float g_hf[NB * NP * 512];
__device__ __align__(16) float g_pooled[NB * 512];
__device__ __align__(16) float g_wab[1024 * 448];
__device__ __align__(16) float g_bias[512];
__device__ __align__(16) __nv_bfloat16 g_s1[NB * NP * KPMAX];   // [hi|lo|hi]
__device__ __align__(16) __nv_bfloat16 g_s2[NB * NP * KPMAX];   // [hi|hi|lo]
__device__ __align__(16) __nv_bfloat16 g_wabs[1024 * KPMAX];    // weights split [hi|hi|lo]

// =================== helpers ===================
__device__ __forceinline__ uint32_t smem_u32(const void* p) {
    uint32_t a;
    asm("{ .reg .u64 t; cvta.to.shared.u64 t, %1; cvt.u32.u64 %0, t; }" : "=r"(a) : "l"(p));
    return a;
}
__device__ __forceinline__ void cpa16(uint32_t s, const void* g) {
    asm volatile("cp.async.cg.shared.global [%0], [%1], 16;" :: "r"(s), "l"(g));
}
#define CP_COMMIT() asm volatile("cp.async.commit_group;")
#define CP_WAIT1()  asm volatile("cp.async.wait_group 1;")
#define CP_WAIT0()  asm volatile("cp.async.wait_group 0;")

__device__ __forceinline__ void ldsm_x4(uint32_t* r, uint32_t addr) {
    asm volatile("ldmatrix.sync.aligned.m8n8.x4.shared.b16 {%0,%1,%2,%3}, [%4];"
        : "=r"(r[0]), "=r"(r[1]), "=r"(r[2]), "=r"(r[3]) : "r"(addr));
}

// =================== bf16 split + fused squared norms ===================
__global__ void split_kernel(const float* __restrict__ src, int ld, int coff, int C,
                             long long bstride, int rows_per_b,
                             __nv_bfloat16* __restrict__ s1,
                             __nv_bfloat16* __restrict__ s2, int Kp,
                             float* __restrict__ xxout)
{
    __shared__ float red[4];
    int r = blockIdx.x;
    int b = r / rows_per_b;
    int ri = r - b * rows_per_b;
    const float* p = src + (long long)b * bstride + (long long)ri * ld + coff;
    __nv_bfloat16* o1 = s1 + (long long)r * Kp;
    __nv_bfloat16* o2 = s2 + (long long)r * Kp;
    __nv_bfloat16 z = __float2bfloat16(0.f);
    float ss = 0.f;
    for (int k = threadIdx.x; k < Kp; k += blockDim.x) {
        __nv_bfloat16 v1 = z, v2 = z;
        if (k < 3 * C) {
            int region = (k < C) ? 0 : ((k < 2 * C) ? 1 : 2);
            int c = k - region * C;
            float x = p[c];
            if (region == 0) ss += x * x;
            __nv_bfloat16 hi = __float2bfloat16(x);
            __nv_bfloat16 lo = __float2bfloat16(x - __bfloat162float(hi));
            v1 = (region == 1) ? lo : hi;
            v2 = (region == 2) ? lo : hi;
        }
        o1[k] = v1;
        o2[k] = v2;
    }
    if (xxout) {
        int lane = threadIdx.x & 31, w = threadIdx.x >> 5;
        #pragma unroll
        for (int o = 16; o; o >>= 1) ss += __shfl_xor_sync(0xffffffffu, ss, o);
        if (!lane) red[w] = ss;
        __syncthreads();
        if (threadIdx.x == 0)
            xxout[r] = red[0] + red[1] + red[2] + red[3];
    }
}

// =================== mma.sync bf16 GEMM, cp.async + ldmatrix ===================
#define SSTR 56          // smem row stride (112B): conflict-free ldmatrix phases
#define ASZ  (128 * SSTR)
#define GEMM_SMEM (4 * ASZ * 2)   // 2 stages x (As+Bs) bf16 = 57344 B

__device__ __forceinline__ void mma16816(float* c, const uint32_t* a, const uint32_t* b)
{
    asm volatile(
        "mma.sync.aligned.m16n8k16.row.col.f32.bf16.bf16.f32 "
        "{%0,%1,%2,%3}, {%4,%5,%6,%7}, {%8,%9}, {%0,%1,%2,%3};"
        : "+f"(c[0]), "+f"(c[1]), "+f"(c[2]), "+f"(c[3])
        : "r"(a[0]), "r"(a[1]), "r"(a[2]), "r"(a[3]), "r"(b[0]), "r"(b[1]));
}

__global__ __launch_bounds__(256, 2) void mma_gemm_kernel(
    const __nv_bfloat16* __restrict__ A,
    const __nv_bfloat16* __restrict__ Bm,
    int Kp, long long bsA, long long bsB,
    const float* __restrict__ xx, int mode,
    float* __restrict__ out, int ldo)
{
    extern __shared__ __align__(16) __nv_bfloat16 sm[];
    __nv_bfloat16* As = sm;             // [2][ASZ]
    __nv_bfloat16* Bs = sm + 2 * ASZ;   // [2][ASZ]

    int b = blockIdx.z;
    int row0 = blockIdx.y * 128;
    int col0 = blockIdx.x * 128;
    int tid = threadIdx.x;
    int wid = tid >> 5, lane = tid & 31;
    int wm = (wid >> 2) * 64;
    int wn = (wid & 3) * 32;

    const __nv_bfloat16* Ab = A + (long long)b * bsA;
    const __nv_bfloat16* Bb = Bm + (long long)b * bsB;

    int lr = tid >> 1;            // tile row this thread loads
    int lc = (tid & 1) * 16;      // element offset 0 or 16

    uint32_t sAraw = smem_u32(As);
    uint32_t sBraw = smem_u32(Bs);
    uint32_t sA0 = sAraw + (uint32_t)(lr * SSTR + lc) * 2;
    uint32_t sB0 = sBraw + (uint32_t)(lr * SSTR + lc) * 2;
    const __nv_bfloat16* gA = Ab + (long long)(row0 + lr) * Kp + lc;
    const __nv_bfloat16* gB = Bb + (long long)(col0 + lr) * Kp + lc;

    // ldmatrix per-lane element offsets (kk=0, frag 0)
    uint32_t a_off = (uint32_t)((wm + (lane & 15)) * SSTR + (lane >> 4) * 8);
    uint32_t b_off = (uint32_t)((wn + (lane & 7) + ((lane >> 4) & 1) * 8) * SSTR
                                + ((lane >> 3) & 1) * 8);

    int nk = Kp >> 5;

    // prologue: stage 0
    cpa16(sA0, gA); cpa16(sA0 + 16, gA + 8);
    cpa16(sB0, gB); cpa16(sB0 + 16, gB + 8);
    CP_COMMIT();

    float acc[4][4][4] = {};

    for (int kc = 0; kc < nk; kc++) {
        int cur = kc & 1;
        if (kc + 1 < nk) {
            int nxt = cur ^ 1;
            const __nv_bfloat16* ga = gA + (kc + 1) * 32;
            const __nv_bfloat16* gb = gB + (kc + 1) * 32;
            uint32_t da = sA0 + (uint32_t)(nxt * ASZ) * 2;
            uint32_t db = sB0 + (uint32_t)(nxt * ASZ) * 2;
            cpa16(da, ga); cpa16(da + 16, ga + 8);
            cpa16(db, gb); cpa16(db + 16, gb + 8);
            CP_COMMIT();
            CP_WAIT1();
        } else {
            CP_WAIT0();
        }
        __syncthreads();

        uint32_t aCur = sAraw + (uint32_t)(cur * ASZ) * 2 + a_off * 2;
        uint32_t bCur = sBraw + (uint32_t)(cur * ASZ) * 2 + b_off * 2;
        #pragma unroll
        for (int kk = 0; kk < 32; kk += 16) {
            uint32_t af[4][4], bq[2][4];
            #pragma unroll
            for (int mf = 0; mf < 4; mf++)
                ldsm_x4(af[mf], aCur + (uint32_t)(mf * 16 * SSTR + kk) * 2);
            #pragma unroll
            for (int nq = 0; nq < 2; nq++)
                ldsm_x4(bq[nq], bCur + (uint32_t)(nq * 16 * SSTR + kk) * 2);
            #pragma unroll
            for (int mf = 0; mf < 4; mf++)
                #pragma unroll
                for (int nf = 0; nf < 4; nf++)
                    mma16816(acc[mf][nf], af[mf], &bq[nf >> 1][(nf & 1) * 2]);
        }
        __syncthreads();
    }

    // -------- epilogue --------
    int ar = lane >> 2, ac = (lane & 3) * 2;
    const float* xxb = (mode == 0) ? (xx + b * NP) : nullptr;
    #pragma unroll
    for (int mf = 0; mf < 4; mf++) {
        int r0g = row0 + wm + mf * 16 + ar;
        #pragma unroll
        for (int nf = 0; nf < 4; nf++) {
            int cg = col0 + wn + nf * 8 + ac;
            float* acc4 = acc[mf][nf];
            if (mode == 0) {
                float xj0 = xxb[cg], xj1 = xxb[cg + 1];
                float xi0 = xxb[r0g], xi1 = xxb[r0g + 8];
                float2 v0, v1;
                v0.x = 2.f * acc4[0] - xi0 - xj0;
                v0.y = 2.f * acc4[1] - xi0 - xj1;
                v1.x = 2.f * acc4[2] - xi1 - xj0;
                v1.y = 2.f * acc4[3] - xi1 - xj1;
                *(float2*)(out + ((long long)b * NP + r0g) * ldo + cg) = v0;
                *(float2*)(out + ((long long)b * NP + r0g + 8) * ldo + cg) = v1;
            } else {
                float2 v0, v1;
                v0.x = acc4[0]; v0.y = acc4[1];
                v1.x = acc4[2]; v1.y = acc4[3];
                *(float2*)(out + ((long long)b * NP + r0g) * ldo + cg) = v0;
                *(float2*)(out + ((long long)b * NP + r0g + 8) * ldo + cg) = v1;
            }
        }
    }
}

// =================== top-20 selection (cached lane-max) ===================
__global__ void topk_kernel(const float* __restrict__ dist, int* __restrict__ idx)
{
    int row = blockIdx.x * (blockDim.x >> 5) + (threadIdx.x >> 5);
    int lane = threadIdx.x & 31;
    if (row >= NB * NP) return;
    const float* d = dist + (size_t)row * NP;
    float v[32];
    #pragma unroll
    for (int s = 0; s < 8; s++) {
        float4 t = *(const float4*)(d + (s * 4) * 32 + lane * 4 - lane * 4);
        // (keep scalar loads; float4 would break the lane-major layout)
        (void)t;
    }
    #pragma unroll
    for (int s = 0; s < 32; s++) v[s] = d[s * 32 + lane];

    float lm = -FLT_MAX; int ls = 0;
    #pragma unroll
    for (int s = 0; s < 32; s++)
        if (v[s] > lm) { lm = v[s]; ls = s; }

    for (int t = 0; t < KNN; t++) {
        float best = lm; int bj = ls * 32 + lane;
        #pragma unroll
        for (int off = 16; off; off >>= 1) {
            float ov = __shfl_xor_sync(0xffffffffu, best, off);
            int oj = __shfl_xor_sync(0xffffffffu, bj, off);
            if (ov > best || (ov == best && oj < bj)) { best = ov; bj = oj; }
        }
        if (lane == 0) idx[row * KNN + t] = bj;
        if ((bj & 31) == lane) {
            int ks = bj >> 5;
            lm = -FLT_MAX; ls = 0;
            #pragma unroll
            for (int s = 0; s < 32; s++) {
                if (s == ks) v[s] = -FLT_MAX;
                if (v[s] > lm) { lm = v[s]; ls = s; }
            }
        }
    }
}

// =================== fold conv weights + BN ===================
__global__ void fold_kernel(const float* __restrict__ W, const float* __restrict__ g,
                            const float* __restrict__ be, const float* __restrict__ m,
                            const float* __restrict__ v, int O, int C,
                            float* __restrict__ wab, float* __restrict__ bias)
{
    int t = blockIdx.x * blockDim.x + threadIdx.x;
    if (t < O * C) {
        int o = t / C, c = t - o * C;
        float s = g[o] / sqrtf(v[o] + 1e-5f);
        float wc = W[o * 2 * C + c];
        float wd = W[o * 2 * C + C + c];
        wab[o * C + c]       = s * (wd - wc);
        wab[(O + o) * C + c] = s * wc;
    }
    if (t < O) bias[t] = be[t] - (g[t] / sqrtf(v[t] + 1e-5f)) * m[t];
}

// =================== edge aggregate ===================
__global__ void aggregate_kernel(const float* __restrict__ ab, int O,
                                 const float* __restrict__ bias,
                                 const int* __restrict__ idx,
                                 float* __restrict__ out, int ldo, int ooff)
{
    int bi = blockIdx.x;
    int b = bi >> 10, i = bi & 1023;
    __shared__ int sj[KNN];
    if (threadIdx.x < KNN) sj[threadIdx.x] = idx[bi * KNN + threadIdx.x];
    __syncthreads();
    const float* abb = ab + (size_t)b * NP * 2 * O;
    for (int o = threadIdx.x; o < O; o += blockDim.x) {
        float a = abb[(size_t)i * 2 * O + o] + bias[o];
        float acc = 0.f;
        #pragma unroll
        for (int k = 0; k < KNN; k++) {
            float val = a + abb[(size_t)sj[k] * 2 * O + O + o];
            acc += fmaxf(val, 0.2f * val);
        }
        out[((size_t)b * NP + i) * ldo + ooff + o] = acc * 0.05f;
    }
}

// =================== pooling + final linear ===================
__global__ void pool_kernel(const float* __restrict__ hf, float* __restrict__ pooled)
{
    int b = blockIdx.x;
    int o = blockIdx.y * blockDim.x + threadIdx.x;
    float s = 0.f;
    for (int i = 0; i < NP; i++) s += hf[((size_t)b * NP + i) * 512 + o];
    pooled[b * 512 + o] = s * (1.f / NP);
}

__global__ void final_kernel(const float* __restrict__ pooled, const float* __restrict__ We,
                             float* __restrict__ out)
{
    int b = blockIdx.x, e = threadIdx.x;
    const float* p = pooled + b * 512;
    const float* w = We + e * 512;
    float s = 0.f;
    for (int o = 0; o < 512; o++) s += p[o] * w[o];
    out[b * 256 + e] = s;
}

// =================== host-side layer driver ===================
// NOTE launch order: weight-only kernels (fold, weight split) go FIRST so the
// dist GEMM is the 4th launch overall in layer 0 -> ncu's sample window lands on it.
static void run_layer(const float* hin, int ld, int coff, int C,
                      const float* W, const float* g, const float* be,
                      const float* m, const float* v, int O,
                      float* outbuf, int ldo, int ooff,
                      float* dist, float* xx, int* idx,
                      float* wab, float* bias, float* ab,
                      __nv_bfloat16* s1, __nv_bfloat16* s2, __nv_bfloat16* wabs)
{
    int Kp = ((3 * C + 63) / 64) * 64;

    fold_kernel<<<(O * C + 255) / 256, 256>>>(W, g, be, m, v, O, C, wab, bias);
    split_kernel<<<2 * O, 128>>>(wab, C, 0, C, 0, 2 * O, wabs, wabs, Kp, nullptr);

    split_kernel<<<NB * NP, 128>>>(hin, ld, coff, C, (long long)NP * ld, NP,
                                   s1, s2, Kp, xx);

    dim3 gd(NP / 128, NP / 128, NB);
    mma_gemm_kernel<<<gd, 256, GEMM_SMEM>>>(s1, s2, Kp,
                                            (long long)NP * Kp, (long long)NP * Kp,
                                            xx, 0, dist, NP);

    topk_kernel<<<NB * NP / 8, 256>>>(dist, idx);

    dim3 gw((2 * O) / 128, NP / 128, NB);
    mma_gemm_kernel<<<gw, 256, GEMM_SMEM>>>(s1, wabs, Kp, (long long)NP * Kp, 0,
                                            nullptr, 1, ab, 2 * O);

    int bt = O < 256 ? O : 256;
    aggregate_kernel<<<NB * NP, bt>>>(ab, O, bias, idx, outbuf, ldo, ooff);
}

extern "C" void kernel_launch(void* const* d_in, const int* in_sizes, int n_in,
                              void* d_out, int out_size)
{
    const float* x  = (const float*)d_in[0];
    const float* W0 = (const float*)d_in[1];
    const float* g0 = (const float*)d_in[2];
    const float* b0 = (const float*)d_in[3];
    const float* m0 = (const float*)d_in[4];
    const float* v0 = (const float*)d_in[5];
    const float* W1 = (const float*)d_in[6];
    const float* g1 = (const float*)d_in[7];
    const float* b1 = (const float*)d_in[8];
    const float* m1 = (const float*)d_in[9];
    const float* v1 = (const float*)d_in[10];
    const float* W2 = (const float*)d_in[11];
    const float* g2 = (const float*)d_in[12];
    const float* b2 = (const float*)d_in[13];
    const float* m2 = (const float*)d_in[14];
    const float* v2 = (const float*)d_in[15];
    const float* Wf = (const float*)d_in[16];
    const float* gf = (const float*)d_in[17];
    const float* bf = (const float*)d_in[18];
    const float* mf = (const float*)d_in[19];
    const float* vf = (const float*)d_in[20];
    const float* We = (const float*)d_in[21];

    float *dist, *xx, *cat, *ab, *hf, *pooled, *wab, *bias;
    int* idx;
    __nv_bfloat16 *s1, *s2, *wabs;
    cudaGetSymbolAddress((void**)&dist,   g_dist);
    cudaGetSymbolAddress((void**)&idx,    g_idx);
    cudaGetSymbolAddress((void**)&xx,     g_xx);
    cudaGetSymbolAddress((void**)&cat,    g_cat);
    cudaGetSymbolAddress((void**)&ab,     g_ab);
    cudaGetSymbolAddress((void**)&hf,     g_hf);
    cudaGetSymbolAddress((void**)&pooled, g_pooled);
    cudaGetSymbolAddress((void**)&wab,    g_wab);
    cudaGetSymbolAddress((void**)&bias,   g_bias);
    cudaGetSymbolAddress((void**)&s1,     g_s1);
    cudaGetSymbolAddress((void**)&s2,     g_s2);
    cudaGetSymbolAddress((void**)&wabs,   g_wabs);

    cudaFuncSetAttribute(mma_gemm_kernel,
                         cudaFuncAttributeMaxDynamicSharedMemorySize, GEMM_SMEM);

    run_layer(x,   3,   0,   3, W0, g0, b0, m0, v0,  64, cat, 448, 0,
              dist, xx, idx, wab, bias, ab, s1, s2, wabs);
    run_layer(cat, 448, 0,  64, W1, g1, b1, m1, v1, 128, cat, 448, 64,
              dist, xx, idx, wab, bias, ab, s1, s2, wabs);
    run_layer(cat, 448, 64, 128, W2, g2, b2, m2, v2, 256, cat, 448, 192,
              dist, xx, idx, wab, bias, ab, s1, s2, wabs);
    run_layer(cat, 448, 0, 448, Wf, gf, bf, mf, vf, 512, hf, 512, 0,
              dist, xx, idx, wab, bias, ab, s1, s2, wabs);

    pool_kernel<<<dim3(NB, 2), 256>>>(hf, pooled);
    final_kernel<<<NB, 256>>>(pooled, We, (float*)d_out);
}

// round 8
// speedup vs baseline: 1.7177x; 1.0812x over previous
#include <cuda_runtime.h>
#include <cuda_bf16.h>
#include <math.h>
#include <float.h>
#include <stdint.h>

#define NB 8
#define NP 1024
#define KNN 20
#define KPMAX 1344   // 3*448 rounded to 64

// ---------------- scratch (device globals; no allocation allowed) ----------------
__device__ __align__(16) float g_dist[NB * NP * NP];            // 32 MB
__device__ __align__(16) int   g_idx[NB * NP * KNN];
__device__ __align__(16) float g_xx[NB * NP];
__device__ __align__(16) float g_cat[NB * NP * 448];
__device__ __align__(16) float g_ab[NB * NP * 1024];
__device__ __align__(16) float g_hf[NB * NP * 512];
__device__ __align__(16) float g_pooled[NB * 512];
__device__ __align__(16) float g_bias[512];
__device__ __align__(16) __nv_bfloat16 g_s1[NB * NP * KPMAX];   // [hi|lo|hi]
__device__ __align__(16) __nv_bfloat16 g_s2[NB * NP * KPMAX];   // [hi|hi|lo]
__device__ __align__(16) __nv_bfloat16 g_wabs[1024 * KPMAX];    // folded weights split [hi|hi|lo]

// =================== helpers ===================
__device__ __forceinline__ uint32_t smem_u32(const void* p) {
    uint32_t a;
    asm("{ .reg .u64 t; cvta.to.shared.u64 t, %1; cvt.u32.u64 %0, t; }" : "=r"(a) : "l"(p));
    return a;
}
__device__ __forceinline__ void cpa16(uint32_t s, const void* g) {
    asm volatile("cp.async.cg.shared.global [%0], [%1], 16;" :: "r"(s), "l"(g));
}
#define CP_COMMIT() asm volatile("cp.async.commit_group;")
#define CP_WAIT2()  asm volatile("cp.async.wait_group 2;")
#define CP_WAIT1()  asm volatile("cp.async.wait_group 1;")
#define CP_WAIT0()  asm volatile("cp.async.wait_group 0;")

__device__ __forceinline__ void ldsm_x4(uint32_t* r, uint32_t addr) {
    asm volatile("ldmatrix.sync.aligned.m8n8.x4.shared.b16 {%0,%1,%2,%3}, [%4];"
        : "=r"(r[0]), "=r"(r[1]), "=r"(r[2]), "=r"(r[3]) : "r"(addr));
}

// =================== feature split (bf16 hi/lo) + fused squared norms ===================
// s1 = [hi | lo | hi], s2 = [hi | hi | lo], zero-padded to Kp.
__global__ void split_kernel(const float* __restrict__ src, int ld, int coff, int C,
                             long long bstride, int rows_per_b,
                             __nv_bfloat16* __restrict__ s1,
                             __nv_bfloat16* __restrict__ s2, int Kp,
                             float* __restrict__ xxout)
{
    __shared__ float red[4];
    int r = blockIdx.x;
    int b = r / rows_per_b;
    int ri = r - b * rows_per_b;
    const float* p = src + (long long)b * bstride + (long long)ri * ld + coff;
    __nv_bfloat16* o1 = s1 + (long long)r * Kp;
    __nv_bfloat16* o2 = s2 + (long long)r * Kp;
    __nv_bfloat16 z = __float2bfloat16(0.f);
    float ss = 0.f;
    for (int k = threadIdx.x; k < Kp; k += blockDim.x) {
        __nv_bfloat16 v1 = z, v2 = z;
        if (k < 3 * C) {
            int region = (k < C) ? 0 : ((k < 2 * C) ? 1 : 2);
            int c = k - region * C;
            float x = p[c];
            if (region == 0) ss += x * x;
            __nv_bfloat16 hi = __float2bfloat16(x);
            __nv_bfloat16 lo = __float2bfloat16(x - __bfloat162float(hi));
            v1 = (region == 1) ? lo : hi;
            v2 = (region == 2) ? lo : hi;
        }
        o1[k] = v1;
        o2[k] = v2;
    }
    int lane = threadIdx.x & 31, w = threadIdx.x >> 5;
    #pragma unroll
    for (int o = 16; o; o >>= 1) ss += __shfl_xor_sync(0xffffffffu, ss, o);
    if (!lane) red[w] = ss;
    __syncthreads();
    if (threadIdx.x == 0)
        xxout[r] = red[0] + red[1] + red[2] + red[3];
}

// =================== fold BN into weights + bf16 split, fused ===================
// wabs row r (< O)  : s*(Wd - Wc) as [hi|hi|lo]   ('a' projection)
// wabs row r (>= O) : s*Wc        as [hi|hi|lo]   ('b' projection)
__global__ void wfoldsplit_kernel(const float* __restrict__ W, const float* __restrict__ g,
                                  const float* __restrict__ be, const float* __restrict__ m,
                                  const float* __restrict__ v, int O, int C, int Kp,
                                  __nv_bfloat16* __restrict__ wabs,
                                  float* __restrict__ bias)
{
    int r = blockIdx.x;                 // 0 .. 2O-1
    bool isA = r < O;
    int o = isA ? r : r - O;
    float s = g[o] * rsqrtf(v[o] + 1e-5f);
    if (threadIdx.x == 0 && isA) bias[o] = be[o] - s * m[o];
    __nv_bfloat16* out = wabs + (long long)r * Kp;
    __nv_bfloat16 z = __float2bfloat16(0.f);
    for (int k = threadIdx.x; k < Kp; k += blockDim.x) {
        __nv_bfloat16 vv = z;
        if (k < 3 * C) {
            int region = (k < C) ? 0 : ((k < 2 * C) ? 1 : 2);
            int c = k - region * C;
            float wc = W[o * 2 * C + c];
            float wd = W[o * 2 * C + C + c];
            float val = isA ? s * (wd - wc) : s * wc;
            __nv_bfloat16 hi = __float2bfloat16(val);
            __nv_bfloat16 lo = __float2bfloat16(val - __bfloat162float(hi));
            vv = (region == 2) ? lo : hi;
        }
        out[k] = vv;
    }
}

// =================== fused mma.sync bf16 GEMM (dist + weight), 3-stage ===================
#define SSTR 56          // smem row stride (112B): conflict-free ldmatrix phases
#define ASZ  (128 * SSTR)
#define NSTAGE 3
#define GEMM_SMEM (NSTAGE * ASZ * 2 * 2)   // 3 stages x (As+Bs) bf16 = 86016 B

__device__ __forceinline__ void mma16816(float* c, const uint32_t* a, const uint32_t* b)
{
    asm volatile(
        "mma.sync.aligned.m16n8k16.row.col.f32.bf16.bf16.f32 "
        "{%0,%1,%2,%3}, {%4,%5,%6,%7}, {%8,%9}, {%0,%1,%2,%3};"
        : "+f"(c[0]), "+f"(c[1]), "+f"(c[2]), "+f"(c[3])
        : "r"(a[0]), "r"(a[1]), "r"(a[2]), "r"(a[3]), "r"(b[0]), "r"(b[1]));
}

// blocks with blockIdx.x < 8:  dist tile, B = s2 (batch-strided), epilogue 2D - xi - xj
// blocks with blockIdx.x >= 8: weight tile, B = wabs (shared), plain store into ab
__global__ __launch_bounds__(256, 2) void mma_gemm_fused(
    const __nv_bfloat16* __restrict__ A,
    const __nv_bfloat16* __restrict__ Bdist,
    const __nv_bfloat16* __restrict__ Bw,
    int Kp, long long bsA, long long bsB,
    const float* __restrict__ xx,
    float* __restrict__ dout,
    float* __restrict__ wout, int ldw)
{
    extern __shared__ __align__(16) __nv_bfloat16 sm[];
    __nv_bfloat16* As = sm;                    // [NSTAGE][ASZ]
    __nv_bfloat16* Bs = sm + NSTAGE * ASZ;     // [NSTAGE][ASZ]

    int b = blockIdx.z;
    int bx = blockIdx.x;
    bool isw = bx >= 8;
    int row0 = blockIdx.y * 128;
    int col0 = (isw ? (bx - 8) : bx) * 128;
    int tid = threadIdx.x;
    int wid = tid >> 5, lane = tid & 31;
    int wm = (wid >> 2) * 64;
    int wn = (wid & 3) * 32;

    const __nv_bfloat16* Ab = A + (long long)b * bsA;
    const __nv_bfloat16* Bb = isw ? Bw : (Bdist + (long long)b * bsB);

    int lr = tid >> 1;            // tile row this thread loads
    int lc = (tid & 1) * 16;      // element offset 0 or 16

    uint32_t sAraw = smem_u32(As);
    uint32_t sBraw = smem_u32(Bs);
    uint32_t sA0 = sAraw + (uint32_t)(lr * SSTR + lc) * 2;
    uint32_t sB0 = sBraw + (uint32_t)(lr * SSTR + lc) * 2;
    const __nv_bfloat16* gA = Ab + (long long)(row0 + lr) * Kp + lc;
    const __nv_bfloat16* gB = Bb + (long long)(col0 + lr) * Kp + lc;

    uint32_t a_off = (uint32_t)((wm + (lane & 15)) * SSTR + (lane >> 4) * 8);
    uint32_t b_off = (uint32_t)((wn + (lane & 7) + ((lane >> 4) & 1) * 8) * SSTR
                                + ((lane >> 3) & 1) * 8);

    int nk = Kp >> 5;

    // prologue: issue up to NSTAGE-1 stages
    #pragma unroll
    for (int s = 0; s < NSTAGE - 1; s++) {
        if (s < nk) {
            uint32_t da = sA0 + (uint32_t)(s * ASZ) * 2;
            uint32_t db = sB0 + (uint32_t)(s * ASZ) * 2;
            const __nv_bfloat16* ga = gA + s * 32;
            const __nv_bfloat16* gb = gB + s * 32;
            cpa16(da, ga); cpa16(da + 16, ga + 8);
            cpa16(db, gb); cpa16(db + 16, gb + 8);
            CP_COMMIT();
        }
    }

    float acc[4][4][4] = {};

    for (int kc = 0; kc < nk; kc++) {
        int cur = kc % NSTAGE;
        if (kc + 2 < nk) {
            int nxt = (kc + 2) % NSTAGE;
            const __nv_bfloat16* ga = gA + (kc + 2) * 32;
            const __nv_bfloat16* gb = gB + (kc + 2) * 32;
            uint32_t da = sA0 + (uint32_t)(nxt * ASZ) * 2;
            uint32_t db = sB0 + (uint32_t)(nxt * ASZ) * 2;
            cpa16(da, ga); cpa16(da + 16, ga + 8);
            cpa16(db, gb); cpa16(db + 16, gb + 8);
            CP_COMMIT();
            CP_WAIT2();
        } else if (kc + 1 < nk) {
            CP_WAIT1();
        } else {
            CP_WAIT0();
        }
        __syncthreads();

        uint32_t aCur = sAraw + (uint32_t)(cur * ASZ) * 2 + a_off * 2;
        uint32_t bCur = sBraw + (uint32_t)(cur * ASZ) * 2 + b_off * 2;
        #pragma unroll
        for (int kk = 0; kk < 32; kk += 16) {
            uint32_t af[4][4], bq[2][4];
            #pragma unroll
            for (int mf = 0; mf < 4; mf++)
                ldsm_x4(af[mf], aCur + (uint32_t)(mf * 16 * SSTR + kk) * 2);
            #pragma unroll
            for (int nq = 0; nq < 2; nq++)
                ldsm_x4(bq[nq], bCur + (uint32_t)(nq * 16 * SSTR + kk) * 2);
            #pragma unroll
            for (int mf = 0; mf < 4; mf++)
                #pragma unroll
                for (int nf = 0; nf < 4; nf++)
                    mma16816(acc[mf][nf], af[mf], &bq[nf >> 1][(nf & 1) * 2]);
        }
        __syncthreads();
    }

    // -------- epilogue --------
    int ar = lane >> 2, ac = (lane & 3) * 2;
    if (!isw) {
        const float* xxb = xx + b * NP;
        #pragma unroll
        for (int mf = 0; mf < 4; mf++) {
            int r0g = row0 + wm + mf * 16 + ar;
            float xi0 = xxb[r0g], xi1 = xxb[r0g + 8];
            #pragma unroll
            for (int nf = 0; nf < 4; nf++) {
                int cg = col0 + wn + nf * 8 + ac;
                float* acc4 = acc[mf][nf];
                float xj0 = xxb[cg], xj1 = xxb[cg + 1];
                float2 v0, v1;
                v0.x = 2.f * acc4[0] - xi0 - xj0;
                v0.y = 2.f * acc4[1] - xi0 - xj1;
                v1.x = 2.f * acc4[2] - xi1 - xj0;
                v1.y = 2.f * acc4[3] - xi1 - xj1;
                *(float2*)(dout + ((long long)b * NP + r0g) * NP + cg) = v0;
                *(float2*)(dout + ((long long)b * NP + r0g + 8) * NP + cg) = v1;
            }
        }
    } else {
        #pragma unroll
        for (int mf = 0; mf < 4; mf++) {
            int r0g = row0 + wm + mf * 16 + ar;
            #pragma unroll
            for (int nf = 0; nf < 4; nf++) {
                int cg = col0 + wn + nf * 8 + ac;
                float* acc4 = acc[mf][nf];
                float2 v0, v1;
                v0.x = acc4[0]; v0.y = acc4[1];
                v1.x = acc4[2]; v1.y = acc4[3];
                *(float2*)(wout + ((long long)b * NP + r0g) * ldw + cg) = v0;
                *(float2*)(wout + ((long long)b * NP + r0g + 8) * ldw + cg) = v1;
            }
        }
    }
}

// =================== top-20 selection (cached lane-max) ===================
__global__ void topk_kernel(const float* __restrict__ dist, int* __restrict__ idx)
{
    int row = blockIdx.x * (blockDim.x >> 5) + (threadIdx.x >> 5);
    int lane = threadIdx.x & 31;
    if (row >= NB * NP) return;
    const float* d = dist + (size_t)row * NP;
    float v[32];
    #pragma unroll
    for (int s = 0; s < 32; s++) v[s] = d[s * 32 + lane];

    float lm = -FLT_MAX; int ls = 0;
    #pragma unroll
    for (int s = 0; s < 32; s++)
        if (v[s] > lm) { lm = v[s]; ls = s; }

    for (int t = 0; t < KNN; t++) {
        float best = lm; int bj = ls * 32 + lane;
        #pragma unroll
        for (int off = 16; off; off >>= 1) {
            float ov = __shfl_xor_sync(0xffffffffu, best, off);
            int oj = __shfl_xor_sync(0xffffffffu, bj, off);
            if (ov > best || (ov == best && oj < bj)) { best = ov; bj = oj; }
        }
        if (lane == 0) idx[row * KNN + t] = bj;
        if ((bj & 31) == lane) {
            int ks = bj >> 5;
            lm = -FLT_MAX; ls = 0;
            #pragma unroll
            for (int s = 0; s < 32; s++) {
                if (s == ks) v[s] = -FLT_MAX;
                if (v[s] > lm) { lm = v[s]; ls = s; }
            }
        }
    }
}

// =================== edge aggregate ===================
__global__ void aggregate_kernel(const float* __restrict__ ab, int O,
                                 const float* __restrict__ bias,
                                 const int* __restrict__ idx,
                                 float* __restrict__ out, int ldo, int ooff)
{
    int bi = blockIdx.x;
    int b = bi >> 10, i = bi & 1023;
    __shared__ int sj[KNN];
    if (threadIdx.x < KNN) sj[threadIdx.x] = idx[bi * KNN + threadIdx.x];
    __syncthreads();
    const float* abb = ab + (size_t)b * NP * 2 * O;
    for (int o = threadIdx.x; o < O; o += blockDim.x) {
        float a = abb[(size_t)i * 2 * O + o] + bias[o];
        float acc = 0.f;
        #pragma unroll
        for (int k = 0; k < KNN; k++) {
            float val = a + abb[(size_t)sj[k] * 2 * O + O + o];
            acc += fmaxf(val, 0.2f * val);
        }
        out[((size_t)b * NP + i) * ldo + ooff + o] = acc * 0.05f;
    }
}

// =================== pooling + final linear ===================
__global__ void pool_kernel(const float* __restrict__ hf, float* __restrict__ pooled)
{
    int b = blockIdx.x;
    int o = blockIdx.y * blockDim.x + threadIdx.x;
    float s = 0.f;
    for (int i = 0; i < NP; i++) s += hf[((size_t)b * NP + i) * 512 + o];
    pooled[b * 512 + o] = s * (1.f / NP);
}

__global__ void final_kernel(const float* __restrict__ pooled, const float* __restrict__ We,
                             float* __restrict__ out)
{
    int b = blockIdx.x, e = threadIdx.x;
    const float* p = pooled + b * 512;
    const float* w = We + e * 512;
    float s = 0.f;
    for (int o = 0; o < 512; o++) s += p[o] * w[o];
    out[b * 256 + e] = s;
}

// =================== host-side layer driver ===================
static void run_layer(const float* hin, int ld, int coff, int C,
                      const float* W, const float* g, const float* be,
                      const float* m, const float* v, int O,
                      float* outbuf, int ldo, int ooff,
                      float* dist, float* xx, int* idx,
                      float* bias, float* ab,
                      __nv_bfloat16* s1, __nv_bfloat16* s2, __nv_bfloat16* wabs)
{
    int Kp = ((3 * C + 63) / 64) * 64;

    wfoldsplit_kernel<<<2 * O, 128>>>(W, g, be, m, v, O, C, Kp, wabs, bias);

    split_kernel<<<NB * NP, 128>>>(hin, ld, coff, C, (long long)NP * ld, NP,
                                   s1, s2, Kp, xx);

    dim3 gd(8 + (2 * O) / 128, NP / 128, NB);
    mma_gemm_fused<<<gd, 256, GEMM_SMEM>>>(s1, s2, wabs, Kp,
                                           (long long)NP * Kp, (long long)NP * Kp,
                                           xx, dist, ab, 2 * O);

    topk_kernel<<<NB * NP / 8, 256>>>(dist, idx);

    int bt = O < 256 ? O : 256;
    aggregate_kernel<<<NB * NP, bt>>>(ab, O, bias, idx, outbuf, ldo, ooff);
}

extern "C" void kernel_launch(void* const* d_in, const int* in_sizes, int n_in,
                              void* d_out, int out_size)
{
    const float* x  = (const float*)d_in[0];
    const float* W0 = (const float*)d_in[1];
    const float* g0 = (const float*)d_in[2];
    const float* b0 = (const float*)d_in[3];
    const float* m0 = (const float*)d_in[4];
    const float* v0 = (const float*)d_in[5];
    const float* W1 = (const float*)d_in[6];
    const float* g1 = (const float*)d_in[7];
    const float* b1 = (const float*)d_in[8];
    const float* m1 = (const float*)d_in[9];
    const float* v1 = (const float*)d_in[10];
    const float* W2 = (const float*)d_in[11];
    const float* g2 = (const float*)d_in[12];
    const float* b2 = (const float*)d_in[13];
    const float* m2 = (const float*)d_in[14];
    const float* v2 = (const float*)d_in[15];
    const float* Wf = (const float*)d_in[16];
    const float* gf = (const float*)d_in[17];
    const float* bf = (const float*)d_in[18];
    const float* mf = (const float*)d_in[19];
    const float* vf = (const float*)d_in[20];
    const float* We = (const float*)d_in[21];

    float *dist, *xx, *cat, *ab, *hf, *pooled, *bias;
    int* idx;
    __nv_bfloat16 *s1, *s2, *wabs;
    cudaGetSymbolAddress((void**)&dist,   g_dist);
    cudaGetSymbolAddress((void**)&idx,    g_idx);
    cudaGetSymbolAddress((void**)&xx,     g_xx);
    cudaGetSymbolAddress((void**)&cat,    g_cat);
    cudaGetSymbolAddress((void**)&ab,     g_ab);
    cudaGetSymbolAddress((void**)&hf,     g_hf);
    cudaGetSymbolAddress((void**)&pooled, g_pooled);
    cudaGetSymbolAddress((void**)&bias,   g_bias);
    cudaGetSymbolAddress((void**)&s1,     g_s1);
    cudaGetSymbolAddress((void**)&s2,     g_s2);
    cudaGetSymbolAddress((void**)&wabs,   g_wabs);

    cudaFuncSetAttribute(mma_gemm_fused,
                         cudaFuncAttributeMaxDynamicSharedMemorySize, GEMM_SMEM);

    run_layer(x,   3,   0,   3, W0, g0, b0, m0, v0,  64, cat, 448, 0,
              dist, xx, idx, bias, ab, s1, s2, wabs);
    run_layer(cat, 448, 0,  64, W1, g1, b1, m1, v1, 128, cat, 448, 64,
              dist, xx, idx, bias, ab, s1, s2, wabs);
    run_layer(cat, 448, 64, 128, W2, g2, b2, m2, v2, 256, cat, 448, 192,
              dist, xx, idx, bias, ab, s1, s2, wabs);
    run_layer(cat, 448, 0, 448, Wf, gf, bf, mf, vf, 512, hf, 512, 0,
              dist, xx, idx, bias, ab, s1, s2, wabs);

    pool_kernel<<<dim3(NB, 2), 256>>>(hf, pooled);
    final_kernel<<<NB, 256>>>(pooled, We, (float*)d_out);
}

// round 9
// speedup vs baseline: 2.0780x; 1.2098x over previous
#include <cuda_runtime.h>
#include <cuda_bf16.h>
#include <math.h>
#include <float.h>
#include <stdint.h>

#define NB 8
#define NP 1024
#define KNN 20
#define KPMAX 1344   // 3*448 rounded to 64

// ---------------- scratch (device globals; no allocation allowed) ----------------
__device__ __align__(16) float g_dist[NB * NP * NP];            // 32 MB
__device__ __align__(16) int   g_idx[NB * NP * KNN];
__device__ __align__(16) float g_xx[NB * NP];
__device__ __align__(16) float g_cat[NB * NP * 448];
__device__ __align__(16) float g_ab[NB * NP * 1024];
__device__ __align__(16) float g_hf[NB * NP * 512];
__device__ __align__(16) float g_pooled[NB * 512];
__device__ __align__(16) float g_bias[512];
__device__ __align__(16) __nv_bfloat16 g_s1[NB * NP * KPMAX];   // [hi|lo|hi]
__device__ __align__(16) __nv_bfloat16 g_s2[NB * NP * KPMAX];   // [hi|hi|lo]
__device__ __align__(16) __nv_bfloat16 g_wabs[1024 * KPMAX];    // folded weights split [hi|hi|lo]

// =================== helpers ===================
__device__ __forceinline__ uint32_t smem_u32(const void* p) {
    uint32_t a;
    asm("{ .reg .u64 t; cvta.to.shared.u64 t, %1; cvt.u32.u64 %0, t; }" : "=r"(a) : "l"(p));
    return a;
}
__device__ __forceinline__ void cpa16(uint32_t s, const void* g) {
    asm volatile("cp.async.cg.shared.global [%0], [%1], 16;" :: "r"(s), "l"(g));
}
#define CP_COMMIT() asm volatile("cp.async.commit_group;")
#define CP_WAIT2()  asm volatile("cp.async.wait_group 2;")
#define CP_WAIT1()  asm volatile("cp.async.wait_group 1;")
#define CP_WAIT0()  asm volatile("cp.async.wait_group 0;")

__device__ __forceinline__ void ldsm_x4(uint32_t* r, uint32_t addr) {
    asm volatile("ldmatrix.sync.aligned.m8n8.x4.shared.b16 {%0,%1,%2,%3}, [%4];"
        : "=r"(r[0]), "=r"(r[1]), "=r"(r[2]), "=r"(r[3]) : "r"(addr));
}

// =================== feature split (bf16 hi/lo) + fused squared norms ===================
__global__ void split_kernel(const float* __restrict__ src, int ld, int coff, int C,
                             long long bstride, int rows_per_b,
                             __nv_bfloat16* __restrict__ s1,
                             __nv_bfloat16* __restrict__ s2, int Kp,
                             float* __restrict__ xxout)
{
    __shared__ float red[4];
    int r = blockIdx.x;
    int b = r / rows_per_b;
    int ri = r - b * rows_per_b;
    const float* p = src + (long long)b * bstride + (long long)ri * ld + coff;
    __nv_bfloat16* o1 = s1 + (long long)r * Kp;
    __nv_bfloat16* o2 = s2 + (long long)r * Kp;
    __nv_bfloat16 z = __float2bfloat16(0.f);
    float ss = 0.f;
    for (int k = threadIdx.x; k < Kp; k += blockDim.x) {
        __nv_bfloat16 v1 = z, v2 = z;
        if (k < 3 * C) {
            int region = (k < C) ? 0 : ((k < 2 * C) ? 1 : 2);
            int c = k - region * C;
            float x = p[c];
            if (region == 0) ss += x * x;
            __nv_bfloat16 hi = __float2bfloat16(x);
            __nv_bfloat16 lo = __float2bfloat16(x - __bfloat162float(hi));
            v1 = (region == 1) ? lo : hi;
            v2 = (region == 2) ? lo : hi;
        }
        o1[k] = v1;
        o2[k] = v2;
    }
    int lane = threadIdx.x & 31, w = threadIdx.x >> 5;
    #pragma unroll
    for (int o = 16; o; o >>= 1) ss += __shfl_xor_sync(0xffffffffu, ss, o);
    if (!lane) red[w] = ss;
    __syncthreads();
    if (threadIdx.x == 0)
        xxout[r] = red[0] + red[1] + red[2] + red[3];
}

// =================== fold BN into weights + bf16 split, fused ===================
__global__ void wfoldsplit_kernel(const float* __restrict__ W, const float* __restrict__ g,
                                  const float* __restrict__ be, const float* __restrict__ m,
                                  const float* __restrict__ v, int O, int C, int Kp,
                                  __nv_bfloat16* __restrict__ wabs,
                                  float* __restrict__ bias)
{
    int r = blockIdx.x;                 // 0 .. 2O-1
    bool isA = r < O;
    int o = isA ? r : r - O;
    float s = g[o] * rsqrtf(v[o] + 1e-5f);
    if (threadIdx.x == 0 && isA) bias[o] = be[o] - s * m[o];
    __nv_bfloat16* out = wabs + (long long)r * Kp;
    __nv_bfloat16 z = __float2bfloat16(0.f);
    for (int k = threadIdx.x; k < Kp; k += blockDim.x) {
        __nv_bfloat16 vv = z;
        if (k < 3 * C) {
            int region = (k < C) ? 0 : ((k < 2 * C) ? 1 : 2);
            int c = k - region * C;
            float wc = W[o * 2 * C + c];
            float wd = W[o * 2 * C + C + c];
            float val = isA ? s * (wd - wc) : s * wc;
            __nv_bfloat16 hi = __float2bfloat16(val);
            __nv_bfloat16 lo = __float2bfloat16(val - __bfloat162float(hi));
            vv = (region == 2) ? lo : hi;
        }
        out[k] = vv;
    }
}

// =================== fused mma.sync bf16 GEMM (dist + weight), 3-stage ===================
#define SSTR 56          // smem row stride (112B): conflict-free ldmatrix phases
#define ASZ  (128 * SSTR)
#define NSTAGE 3
#define GEMM_SMEM (NSTAGE * ASZ * 2 * 2)   // 3 stages x (As+Bs) bf16 = 86016 B

__device__ __forceinline__ void mma16816(float* c, const uint32_t* a, const uint32_t* b)
{
    asm volatile(
        "mma.sync.aligned.m16n8k16.row.col.f32.bf16.bf16.f32 "
        "{%0,%1,%2,%3}, {%4,%5,%6,%7}, {%8,%9}, {%0,%1,%2,%3};"
        : "+f"(c[0]), "+f"(c[1]), "+f"(c[2]), "+f"(c[3])
        : "r"(a[0]), "r"(a[1]), "r"(a[2]), "r"(a[3]), "r"(b[0]), "r"(b[1]));
}

__global__ __launch_bounds__(256, 2) void mma_gemm_fused(
    const __nv_bfloat16* __restrict__ A,
    const __nv_bfloat16* __restrict__ Bdist,
    const __nv_bfloat16* __restrict__ Bw,
    int Kp, long long bsA, long long bsB,
    const float* __restrict__ xx,
    float* __restrict__ dout,
    float* __restrict__ wout, int ldw)
{
    extern __shared__ __align__(16) __nv_bfloat16 sm[];
    __nv_bfloat16* As = sm;                    // [NSTAGE][ASZ]
    __nv_bfloat16* Bs = sm + NSTAGE * ASZ;     // [NSTAGE][ASZ]

    int b = blockIdx.z;
    int bx = blockIdx.x;
    bool isw = bx >= 8;
    int row0 = blockIdx.y * 128;
    int col0 = (isw ? (bx - 8) : bx) * 128;
    int tid = threadIdx.x;
    int wid = tid >> 5, lane = tid & 31;
    int wm = (wid >> 2) * 64;
    int wn = (wid & 3) * 32;

    const __nv_bfloat16* Ab = A + (long long)b * bsA;
    const __nv_bfloat16* Bb = isw ? Bw : (Bdist + (long long)b * bsB);

    int lr = tid >> 1;
    int lc = (tid & 1) * 16;

    uint32_t sAraw = smem_u32(As);
    uint32_t sBraw = smem_u32(Bs);
    uint32_t sA0 = sAraw + (uint32_t)(lr * SSTR + lc) * 2;
    uint32_t sB0 = sBraw + (uint32_t)(lr * SSTR + lc) * 2;
    const __nv_bfloat16* gA = Ab + (long long)(row0 + lr) * Kp + lc;
    const __nv_bfloat16* gB = Bb + (long long)(col0 + lr) * Kp + lc;

    uint32_t a_off = (uint32_t)((wm + (lane & 15)) * SSTR + (lane >> 4) * 8);
    uint32_t b_off = (uint32_t)((wn + (lane & 7) + ((lane >> 4) & 1) * 8) * SSTR
                                + ((lane >> 3) & 1) * 8);

    int nk = Kp >> 5;

    #pragma unroll
    for (int s = 0; s < NSTAGE - 1; s++) {
        if (s < nk) {
            uint32_t da = sA0 + (uint32_t)(s * ASZ) * 2;
            uint32_t db = sB0 + (uint32_t)(s * ASZ) * 2;
            const __nv_bfloat16* ga = gA + s * 32;
            const __nv_bfloat16* gb = gB + s * 32;
            cpa16(da, ga); cpa16(da + 16, ga + 8);
            cpa16(db, gb); cpa16(db + 16, gb + 8);
            CP_COMMIT();
        }
    }

    float acc[4][4][4] = {};

    for (int kc = 0; kc < nk; kc++) {
        int cur = kc % NSTAGE;
        if (kc + 2 < nk) {
            int nxt = (kc + 2) % NSTAGE;
            const __nv_bfloat16* ga = gA + (kc + 2) * 32;
            const __nv_bfloat16* gb = gB + (kc + 2) * 32;
            uint32_t da = sA0 + (uint32_t)(nxt * ASZ) * 2;
            uint32_t db = sB0 + (uint32_t)(nxt * ASZ) * 2;
            cpa16(da, ga); cpa16(da + 16, ga + 8);
            cpa16(db, gb); cpa16(db + 16, gb + 8);
            CP_COMMIT();
            CP_WAIT2();
        } else if (kc + 1 < nk) {
            CP_WAIT1();
        } else {
            CP_WAIT0();
        }
        __syncthreads();

        uint32_t aCur = sAraw + (uint32_t)(cur * ASZ) * 2 + a_off * 2;
        uint32_t bCur = sBraw + (uint32_t)(cur * ASZ) * 2 + b_off * 2;
        #pragma unroll
        for (int kk = 0; kk < 32; kk += 16) {
            uint32_t af[4][4], bq[2][4];
            #pragma unroll
            for (int mf = 0; mf < 4; mf++)
                ldsm_x4(af[mf], aCur + (uint32_t)(mf * 16 * SSTR + kk) * 2);
            #pragma unroll
            for (int nq = 0; nq < 2; nq++)
                ldsm_x4(bq[nq], bCur + (uint32_t)(nq * 16 * SSTR + kk) * 2);
            #pragma unroll
            for (int mf = 0; mf < 4; mf++)
                #pragma unroll
                for (int nf = 0; nf < 4; nf++)
                    mma16816(acc[mf][nf], af[mf], &bq[nf >> 1][(nf & 1) * 2]);
        }
        __syncthreads();
    }

    // -------- epilogue --------
    int ar = lane >> 2, ac = (lane & 3) * 2;
    if (!isw) {
        const float* xxb = xx + b * NP;
        #pragma unroll
        for (int mf = 0; mf < 4; mf++) {
            int r0g = row0 + wm + mf * 16 + ar;
            float xi0 = xxb[r0g], xi1 = xxb[r0g + 8];
            #pragma unroll
            for (int nf = 0; nf < 4; nf++) {
                int cg = col0 + wn + nf * 8 + ac;
                float* acc4 = acc[mf][nf];
                float xj0 = xxb[cg], xj1 = xxb[cg + 1];
                float2 v0, v1;
                v0.x = 2.f * acc4[0] - xi0 - xj0;
                v0.y = 2.f * acc4[1] - xi0 - xj1;
                v1.x = 2.f * acc4[2] - xi1 - xj0;
                v1.y = 2.f * acc4[3] - xi1 - xj1;
                *(float2*)(dout + ((long long)b * NP + r0g) * NP + cg) = v0;
                *(float2*)(dout + ((long long)b * NP + r0g + 8) * NP + cg) = v1;
            }
        }
    } else {
        #pragma unroll
        for (int mf = 0; mf < 4; mf++) {
            int r0g = row0 + wm + mf * 16 + ar;
            #pragma unroll
            for (int nf = 0; nf < 4; nf++) {
                int cg = col0 + wn + nf * 8 + ac;
                float* acc4 = acc[mf][nf];
                float2 v0, v1;
                v0.x = acc4[0]; v0.y = acc4[1];
                v1.x = acc4[2]; v1.y = acc4[3];
                *(float2*)(wout + ((long long)b * NP + r0g) * ldw + cg) = v0;
                *(float2*)(wout + ((long long)b * NP + r0g + 8) * ldw + cg) = v1;
            }
        }
    }
}

// =================== top-20: sorted per-lane top-4 queues + exact verify ===================
__global__ void topk_kernel(const float* __restrict__ dist, int* __restrict__ idx)
{
    int row = blockIdx.x * (blockDim.x >> 5) + (threadIdx.x >> 5);
    int lane = threadIdx.x & 31;
    if (row >= NB * NP) return;
    const float* d = dist + (size_t)row * NP;
    float v[32];
    #pragma unroll
    for (int s = 0; s < 32; s++) v[s] = d[s * 32 + lane];

    // build per-lane sorted top-4 (desc) of own 32 slots
    float m0 = -FLT_MAX, m1 = -FLT_MAX, m2 = -FLT_MAX, m3 = -FLT_MAX;
    int q0 = 0, q1 = 0, q2 = 0, q3 = 0;
    #pragma unroll
    for (int s = 0; s < 32; s++) {
        float x = v[s];
        if (x > m3) {
            if (x > m0)      { m3 = m2; q3 = q2; m2 = m1; q2 = q1; m1 = m0; q1 = q0; m0 = x; q0 = s; }
            else if (x > m1) { m3 = m2; q3 = q2; m2 = m1; q2 = q1; m1 = x;  q1 = s; }
            else if (x > m2) { m3 = m2; q3 = q2; m2 = x;  q2 = s; }
            else             { m3 = x;  q3 = s; }
        }
    }

    // greedy selection: lane's max remaining candidate is always m0 (sorted queue)
    float thresh = 0.f;
    #pragma unroll
    for (int t = 0; t < KNN; t++) {
        float best = m0;
        #pragma unroll
        for (int off = 16; off; off >>= 1)
            best = fmaxf(best, __shfl_xor_sync(0xffffffffu, best, off));
        unsigned mask = __ballot_sync(0xffffffffu, m0 == best);
        int wl = __ffs(mask) - 1;
        int wq = __shfl_sync(0xffffffffu, q0, wl);
        if (lane == 0) idx[row * KNN + t] = wq * 32 + wl;
        if (lane == wl) { m0 = m1; q0 = q1; m1 = m2; q1 = q2; m2 = m3; q2 = q3; m3 = -FLT_MAX; }
        thresh = best;
    }

    // exact verify: correct iff exactly 19 values in the row are strictly > thresh
    int cnt = 0;
    #pragma unroll
    for (int s = 0; s < 32; s++) cnt += (v[s] > thresh) ? 1 : 0;
    cnt = __reduce_add_sync(0xffffffffu, cnt);
    if (cnt == 19) return;

    // -------- rare fallback: exact iterative selection (R4-style) --------
    for (int t = 0; t < KNN; t++) {
        float best = -FLT_MAX; int bs = 0;
        #pragma unroll
        for (int s = 0; s < 32; s++)
            if (v[s] > best) { best = v[s]; bs = s; }
        int bj = bs * 32 + lane;
        #pragma unroll
        for (int off = 16; off; off >>= 1) {
            float ov = __shfl_xor_sync(0xffffffffu, best, off);
            int oj = __shfl_xor_sync(0xffffffffu, bj, off);
            if (ov > best || (ov == best && oj < bj)) { best = ov; bj = oj; }
        }
        if (lane == 0) idx[row * KNN + t] = bj;
        if ((bj & 31) == lane) {
            int ks = bj >> 5;
            #pragma unroll
            for (int s = 0; s < 32; s++)
                if (s == ks) v[s] = -FLT_MAX;
        }
    }
}

// =================== edge aggregate ===================
__global__ void aggregate_kernel(const float* __restrict__ ab, int O,
                                 const float* __restrict__ bias,
                                 const int* __restrict__ idx,
                                 float* __restrict__ out, int ldo, int ooff)
{
    int bi = blockIdx.x;
    int b = bi >> 10, i = bi & 1023;
    __shared__ int sj[KNN];
    if (threadIdx.x < KNN) sj[threadIdx.x] = idx[bi * KNN + threadIdx.x];
    __syncthreads();
    const float* abb = ab + (size_t)b * NP * 2 * O;
    for (int o = threadIdx.x; o < O; o += blockDim.x) {
        float a = abb[(size_t)i * 2 * O + o] + bias[o];
        float acc = 0.f;
        #pragma unroll
        for (int k = 0; k < KNN; k++) {
            float val = a + abb[(size_t)sj[k] * 2 * O + O + o];
            acc += fmaxf(val, 0.2f * val);
        }
        out[((size_t)b * NP + i) * ldo + ooff + o] = acc * 0.05f;
    }
}

// =================== pooling + final linear ===================
__global__ void pool_kernel(const float* __restrict__ hf, float* __restrict__ pooled)
{
    int b = blockIdx.x;
    int o = blockIdx.y * blockDim.x + threadIdx.x;
    float s = 0.f;
    for (int i = 0; i < NP; i++) s += hf[((size_t)b * NP + i) * 512 + o];
    pooled[b * 512 + o] = s * (1.f / NP);
}

__global__ void final_kernel(const float* __restrict__ pooled, const float* __restrict__ We,
                             float* __restrict__ out)
{
    int b = blockIdx.x, e = threadIdx.x;
    const float* p = pooled + b * 512;
    const float* w = We + e * 512;
    float s = 0.f;
    for (int o = 0; o < 512; o++) s += p[o] * w[o];
    out[b * 256 + e] = s;
}

// =================== host-side layer driver ===================
static void run_layer(const float* hin, int ld, int coff, int C,
                      const float* W, const float* g, const float* be,
                      const float* m, const float* v, int O,
                      float* outbuf, int ldo, int ooff,
                      float* dist, float* xx, int* idx,
                      float* bias, float* ab,
                      __nv_bfloat16* s1, __nv_bfloat16* s2, __nv_bfloat16* wabs)
{
    int Kp = ((3 * C + 63) / 64) * 64;

    wfoldsplit_kernel<<<2 * O, 128>>>(W, g, be, m, v, O, C, Kp, wabs, bias);

    split_kernel<<<NB * NP, 128>>>(hin, ld, coff, C, (long long)NP * ld, NP,
                                   s1, s2, Kp, xx);

    dim3 gd(8 + (2 * O) / 128, NP / 128, NB);
    mma_gemm_fused<<<gd, 256, GEMM_SMEM>>>(s1, s2, wabs, Kp,
                                           (long long)NP * Kp, (long long)NP * Kp,
                                           xx, dist, ab, 2 * O);

    topk_kernel<<<NB * NP / 8, 256>>>(dist, idx);

    int bt = O < 256 ? O : 256;
    aggregate_kernel<<<NB * NP, bt>>>(ab, O, bias, idx, outbuf, ldo, ooff);
}

extern "C" void kernel_launch(void* const* d_in, const int* in_sizes, int n_in,
                              void* d_out, int out_size)
{
    const float* x  = (const float*)d_in[0];
    const float* W0 = (const float*)d_in[1];
    const float* g0 = (const float*)d_in[2];
    const float* b0 = (const float*)d_in[3];
    const float* m0 = (const float*)d_in[4];
    const float* v0 = (const float*)d_in[5];
    const float* W1 = (const float*)d_in[6];
    const float* g1 = (const float*)d_in[7];
    const float* b1 = (const float*)d_in[8];
    const float* m1 = (const float*)d_in[9];
    const float* v1 = (const float*)d_in[10];
    const float* W2 = (const float*)d_in[11];
    const float* g2 = (const float*)d_in[12];
    const float* b2 = (const float*)d_in[13];
    const float* m2 = (const float*)d_in[14];
    const float* v2 = (const float*)d_in[15];
    const float* Wf = (const float*)d_in[16];
    const float* gf = (const float*)d_in[17];
    const float* bf = (const float*)d_in[18];
    const float* mf = (const float*)d_in[19];
    const float* vf = (const float*)d_in[20];
    const float* We = (const float*)d_in[21];

    float *dist, *xx, *cat, *ab, *hf, *pooled, *bias;
    int* idx;
    __nv_bfloat16 *s1, *s2, *wabs;
    cudaGetSymbolAddress((void**)&dist,   g_dist);
    cudaGetSymbolAddress((void**)&idx,    g_idx);
    cudaGetSymbolAddress((void**)&xx,     g_xx);
    cudaGetSymbolAddress((void**)&cat,    g_cat);
    cudaGetSymbolAddress((void**)&ab,     g_ab);
    cudaGetSymbolAddress((void**)&hf,     g_hf);
    cudaGetSymbolAddress((void**)&pooled, g_pooled);
    cudaGetSymbolAddress((void**)&bias,   g_bias);
    cudaGetSymbolAddress((void**)&s1,     g_s1);
    cudaGetSymbolAddress((void**)&s2,     g_s2);
    cudaGetSymbolAddress((void**)&wabs,   g_wabs);

    cudaFuncSetAttribute(mma_gemm_fused,
                         cudaFuncAttributeMaxDynamicSharedMemorySize, GEMM_SMEM);

    run_layer(x,   3,   0,   3, W0, g0, b0, m0, v0,  64, cat, 448, 0,
              dist, xx, idx, bias, ab, s1, s2, wabs);
    run_layer(cat, 448, 0,  64, W1, g1, b1, m1, v1, 128, cat, 448, 64,
              dist, xx, idx, bias, ab, s1, s2, wabs);
    run_layer(cat, 448, 64, 128, W2, g2, b2, m2, v2, 256, cat, 448, 192,
              dist, xx, idx, bias, ab, s1, s2, wabs);
    run_layer(cat, 448, 0, 448, Wf, gf, bf, mf, vf, 512, hf, 512, 0,
              dist, xx, idx, bias, ab, s1, s2, wabs);

    pool_kernel<<<dim3(NB, 2), 256>>>(hf, pooled);
    final_kernel<<<NB, 256>>>(pooled, We, (float*)d_out);
}

// round 10
// speedup vs baseline: 2.1054x; 1.0132x over previous
#include <cuda_runtime.h>
#include <cuda_bf16.h>
#include <math.h>
#include <float.h>
#include <stdint.h>

#define NB 8
#define NP 1024
#define KNN 20
#define KPMAX 1344   // 3*448 rounded to 64

// ---------------- scratch (device globals; no allocation allowed) ----------------
__device__ __align__(16) float g_dist[NB * NP * NP];            // 32 MB
__device__ __align__(16) int   g_idx[NB * NP * KNN];
__device__ __align__(16) float g_xx[NB * NP];
__device__ __align__(16) float g_cat[NB * NP * 448];
__device__ __align__(16) float g_ab[NB * NP * 1024];
__device__ __align__(16) float g_hf[NB * NP * 512];
__device__ __align__(16) float g_pooled[NB * 512];
__device__ __align__(16) float g_bias4[4 * 512];
__device__ __align__(16) __nv_bfloat16 g_s1[NB * NP * KPMAX];   // [hi|lo|hi]
__device__ __align__(16) __nv_bfloat16 g_s2[NB * NP * KPMAX];   // [hi|hi|lo]
__device__ __align__(16) __nv_bfloat16 g_wabs4[4][1024 * KPMAX]; // per-layer folded weights

// =================== helpers ===================
__device__ __forceinline__ uint32_t smem_u32(const void* p) {
    uint32_t a;
    asm("{ .reg .u64 t; cvta.to.shared.u64 t, %1; cvt.u32.u64 %0, t; }" : "=r"(a) : "l"(p));
    return a;
}
__device__ __forceinline__ void cpa16(uint32_t s, const void* g) {
    asm volatile("cp.async.cg.shared.global [%0], [%1], 16;" :: "r"(s), "l"(g));
}
#define CP_COMMIT() asm volatile("cp.async.commit_group;")
#define CP_WAIT2()  asm volatile("cp.async.wait_group 2;")
#define CP_WAIT1()  asm volatile("cp.async.wait_group 1;")
#define CP_WAIT0()  asm volatile("cp.async.wait_group 0;")

__device__ __forceinline__ void ldsm_x4(uint32_t* r, uint32_t addr) {
    asm volatile("ldmatrix.sync.aligned.m8n8.x4.shared.b16 {%0,%1,%2,%3}, [%4];"
        : "=r"(r[0]), "=r"(r[1]), "=r"(r[2]), "=r"(r[3]) : "r"(addr));
}

// =================== feature split (bf16 hi/lo) + fused squared norms ===================
__global__ void split_kernel(const float* __restrict__ src, int ld, int coff, int C,
                             long long bstride, int rows_per_b,
                             __nv_bfloat16* __restrict__ s1,
                             __nv_bfloat16* __restrict__ s2, int Kp,
                             float* __restrict__ xxout)
{
    __shared__ float red[4];
    int r = blockIdx.x;
    int b = r / rows_per_b;
    int ri = r - b * rows_per_b;
    const float* p = src + (long long)b * bstride + (long long)ri * ld + coff;
    __nv_bfloat16* o1 = s1 + (long long)r * Kp;
    __nv_bfloat16* o2 = s2 + (long long)r * Kp;
    __nv_bfloat16 z = __float2bfloat16(0.f);
    float ss = 0.f;
    for (int k = threadIdx.x; k < Kp; k += blockDim.x) {
        __nv_bfloat16 v1 = z, v2 = z;
        if (k < 3 * C) {
            int region = (k < C) ? 0 : ((k < 2 * C) ? 1 : 2);
            int c = k - region * C;
            float x = p[c];
            if (region == 0) ss += x * x;
            __nv_bfloat16 hi = __float2bfloat16(x);
            __nv_bfloat16 lo = __float2bfloat16(x - __bfloat162float(hi));
            v1 = (region == 1) ? lo : hi;
            v2 = (region == 2) ? lo : hi;
        }
        o1[k] = v1;
        o2[k] = v2;
    }
    int lane = threadIdx.x & 31, w = threadIdx.x >> 5;
    #pragma unroll
    for (int o = 16; o; o >>= 1) ss += __shfl_xor_sync(0xffffffffu, ss, o);
    if (!lane) red[w] = ss;
    __syncthreads();
    if (threadIdx.x == 0)
        xxout[r] = red[0] + red[1] + red[2] + red[3];
}

// =================== fold BN into weights + bf16 split, fused ===================
__global__ void wfoldsplit_kernel(const float* __restrict__ W, const float* __restrict__ g,
                                  const float* __restrict__ be, const float* __restrict__ m,
                                  const float* __restrict__ v, int O, int C, int Kp,
                                  __nv_bfloat16* __restrict__ wabs,
                                  float* __restrict__ bias)
{
    int r = blockIdx.x;                 // 0 .. 2O-1
    bool isA = r < O;
    int o = isA ? r : r - O;
    float s = g[o] * rsqrtf(v[o] + 1e-5f);
    if (threadIdx.x == 0 && isA) bias[o] = be[o] - s * m[o];
    __nv_bfloat16* out = wabs + (long long)r * Kp;
    __nv_bfloat16 z = __float2bfloat16(0.f);
    for (int k = threadIdx.x; k < Kp; k += blockDim.x) {
        __nv_bfloat16 vv = z;
        if (k < 3 * C) {
            int region = (k < C) ? 0 : ((k < 2 * C) ? 1 : 2);
            int c = k - region * C;
            float wc = W[o * 2 * C + c];
            float wd = W[o * 2 * C + C + c];
            float val = isA ? s * (wd - wc) : s * wc;
            __nv_bfloat16 hi = __float2bfloat16(val);
            __nv_bfloat16 lo = __float2bfloat16(val - __bfloat162float(hi));
            vv = (region == 2) ? lo : hi;
        }
        out[k] = vv;
    }
}

// =================== mma.sync bf16 GEMM, 3-stage cp.async + ldmatrix ===================
#define SSTR 56          // smem row stride (112B): conflict-free ldmatrix phases
#define ASZ  (128 * SSTR)
#define NSTAGE 3
#define GEMM_SMEM (NSTAGE * ASZ * 2 * 2)   // 3 stages x (As+Bs) bf16 = 86016 B

__device__ __forceinline__ void mma16816(float* c, const uint32_t* a, const uint32_t* b)
{
    asm volatile(
        "mma.sync.aligned.m16n8k16.row.col.f32.bf16.bf16.f32 "
        "{%0,%1,%2,%3}, {%4,%5,%6,%7}, {%8,%9}, {%0,%1,%2,%3};"
        : "+f"(c[0]), "+f"(c[1]), "+f"(c[2]), "+f"(c[3])
        : "r"(a[0]), "r"(a[1]), "r"(a[2]), "r"(a[3]), "r"(b[0]), "r"(b[1]));
}

// mode 0: out = 2*D - xx_i - xx_j (dist). mode 1: plain store (weight projection).
__global__ __launch_bounds__(256, 2) void mma_gemm_kernel(
    const __nv_bfloat16* __restrict__ A,
    const __nv_bfloat16* __restrict__ Bm,
    int Kp, long long bsA, long long bsB,
    const float* __restrict__ xx, int mode,
    float* __restrict__ out, int ldo)
{
    extern __shared__ __align__(16) __nv_bfloat16 sm[];
    __nv_bfloat16* As = sm;                    // [NSTAGE][ASZ]
    __nv_bfloat16* Bs = sm + NSTAGE * ASZ;     // [NSTAGE][ASZ]

    int b = blockIdx.z;
    int row0 = blockIdx.y * 128;
    int col0 = blockIdx.x * 128;
    int tid = threadIdx.x;
    int wid = tid >> 5, lane = tid & 31;
    int wm = (wid >> 2) * 64;
    int wn = (wid & 3) * 32;

    const __nv_bfloat16* Ab = A + (long long)b * bsA;
    const __nv_bfloat16* Bb = Bm + (long long)b * bsB;

    int lr = tid >> 1;
    int lc = (tid & 1) * 16;

    uint32_t sAraw = smem_u32(As);
    uint32_t sBraw = smem_u32(Bs);
    uint32_t sA0 = sAraw + (uint32_t)(lr * SSTR + lc) * 2;
    uint32_t sB0 = sBraw + (uint32_t)(lr * SSTR + lc) * 2;
    const __nv_bfloat16* gA = Ab + (long long)(row0 + lr) * Kp + lc;
    const __nv_bfloat16* gB = Bb + (long long)(col0 + lr) * Kp + lc;

    uint32_t a_off = (uint32_t)((wm + (lane & 15)) * SSTR + (lane >> 4) * 8);
    uint32_t b_off = (uint32_t)((wn + (lane & 7) + ((lane >> 4) & 1) * 8) * SSTR
                                + ((lane >> 3) & 1) * 8);

    int nk = Kp >> 5;

    #pragma unroll
    for (int s = 0; s < NSTAGE - 1; s++) {
        if (s < nk) {
            uint32_t da = sA0 + (uint32_t)(s * ASZ) * 2;
            uint32_t db = sB0 + (uint32_t)(s * ASZ) * 2;
            const __nv_bfloat16* ga = gA + s * 32;
            const __nv_bfloat16* gb = gB + s * 32;
            cpa16(da, ga); cpa16(da + 16, ga + 8);
            cpa16(db, gb); cpa16(db + 16, gb + 8);
            CP_COMMIT();
        }
    }

    float acc[4][4][4] = {};

    for (int kc = 0; kc < nk; kc++) {
        int cur = kc % NSTAGE;
        if (kc + 2 < nk) {
            int nxt = (kc + 2) % NSTAGE;
            const __nv_bfloat16* ga = gA + (kc + 2) * 32;
            const __nv_bfloat16* gb = gB + (kc + 2) * 32;
            uint32_t da = sA0 + (uint32_t)(nxt * ASZ) * 2;
            uint32_t db = sB0 + (uint32_t)(nxt * ASZ) * 2;
            cpa16(da, ga); cpa16(da + 16, ga + 8);
            cpa16(db, gb); cpa16(db + 16, gb + 8);
            CP_COMMIT();
            CP_WAIT2();
        } else if (kc + 1 < nk) {
            CP_WAIT1();
        } else {
            CP_WAIT0();
        }
        __syncthreads();

        uint32_t aCur = sAraw + (uint32_t)(cur * ASZ) * 2 + a_off * 2;
        uint32_t bCur = sBraw + (uint32_t)(cur * ASZ) * 2 + b_off * 2;
        #pragma unroll
        for (int kk = 0; kk < 32; kk += 16) {
            uint32_t af[4][4], bq[2][4];
            #pragma unroll
            for (int mf = 0; mf < 4; mf++)
                ldsm_x4(af[mf], aCur + (uint32_t)(mf * 16 * SSTR + kk) * 2);
            #pragma unroll
            for (int nq = 0; nq < 2; nq++)
                ldsm_x4(bq[nq], bCur + (uint32_t)(nq * 16 * SSTR + kk) * 2);
            #pragma unroll
            for (int mf = 0; mf < 4; mf++)
                #pragma unroll
                for (int nf = 0; nf < 4; nf++)
                    mma16816(acc[mf][nf], af[mf], &bq[nf >> 1][(nf & 1) * 2]);
        }
        __syncthreads();
    }

    // -------- epilogue --------
    int ar = lane >> 2, ac = (lane & 3) * 2;
    if (mode == 0) {
        const float* xxb = xx + b * NP;
        #pragma unroll
        for (int mf = 0; mf < 4; mf++) {
            int r0g = row0 + wm + mf * 16 + ar;
            float xi0 = xxb[r0g], xi1 = xxb[r0g + 8];
            #pragma unroll
            for (int nf = 0; nf < 4; nf++) {
                int cg = col0 + wn + nf * 8 + ac;
                float* acc4 = acc[mf][nf];
                float xj0 = xxb[cg], xj1 = xxb[cg + 1];
                float2 v0, v1;
                v0.x = 2.f * acc4[0] - xi0 - xj0;
                v0.y = 2.f * acc4[1] - xi0 - xj1;
                v1.x = 2.f * acc4[2] - xi1 - xj0;
                v1.y = 2.f * acc4[3] - xi1 - xj1;
                *(float2*)(out + ((long long)b * NP + r0g) * ldo + cg) = v0;
                *(float2*)(out + ((long long)b * NP + r0g + 8) * ldo + cg) = v1;
            }
        }
    } else {
        #pragma unroll
        for (int mf = 0; mf < 4; mf++) {
            int r0g = row0 + wm + mf * 16 + ar;
            #pragma unroll
            for (int nf = 0; nf < 4; nf++) {
                int cg = col0 + wn + nf * 8 + ac;
                float* acc4 = acc[mf][nf];
                float2 v0, v1;
                v0.x = acc4[0]; v0.y = acc4[1];
                v1.x = acc4[2]; v1.y = acc4[3];
                *(float2*)(out + ((long long)b * NP + r0g) * ldo + cg) = v0;
                *(float2*)(out + ((long long)b * NP + r0g + 8) * ldo + cg) = v1;
            }
        }
    }
}

// =================== top-20: sorted per-lane top-4 queues + exact verify ===================
__global__ void topk_kernel(const float* __restrict__ dist, int* __restrict__ idx)
{
    int row = blockIdx.x * (blockDim.x >> 5) + (threadIdx.x >> 5);
    int lane = threadIdx.x & 31;
    if (row >= NB * NP) return;
    const float* d = dist + (size_t)row * NP;
    float v[32];
    #pragma unroll
    for (int s = 0; s < 32; s++) v[s] = d[s * 32 + lane];

    float m0 = -FLT_MAX, m1 = -FLT_MAX, m2 = -FLT_MAX, m3 = -FLT_MAX;
    int q0 = 0, q1 = 0, q2 = 0, q3 = 0;
    #pragma unroll
    for (int s = 0; s < 32; s++) {
        float x = v[s];
        if (x > m3) {
            if (x > m0)      { m3 = m2; q3 = q2; m2 = m1; q2 = q1; m1 = m0; q1 = q0; m0 = x; q0 = s; }
            else if (x > m1) { m3 = m2; q3 = q2; m2 = m1; q2 = q1; m1 = x;  q1 = s; }
            else if (x > m2) { m3 = m2; q3 = q2; m2 = x;  q2 = s; }
            else             { m3 = x;  q3 = s; }
        }
    }

    float thresh = 0.f;
    #pragma unroll
    for (int t = 0; t < KNN; t++) {
        float best = m0;
        #pragma unroll
        for (int off = 16; off; off >>= 1)
            best = fmaxf(best, __shfl_xor_sync(0xffffffffu, best, off));
        unsigned mask = __ballot_sync(0xffffffffu, m0 == best);
        int wl = __ffs(mask) - 1;
        int wq = __shfl_sync(0xffffffffu, q0, wl);
        if (lane == 0) idx[row * KNN + t] = wq * 32 + wl;
        if (lane == wl) { m0 = m1; q0 = q1; m1 = m2; q1 = q2; m2 = m3; q2 = q3; m3 = -FLT_MAX; }
        thresh = best;
    }

    int cnt = 0;
    #pragma unroll
    for (int s = 0; s < 32; s++) cnt += (v[s] > thresh) ? 1 : 0;
    cnt = __reduce_add_sync(0xffffffffu, cnt);
    if (cnt == 19) return;

    // rare fallback: exact iterative selection
    for (int t = 0; t < KNN; t++) {
        float best = -FLT_MAX; int bs = 0;
        #pragma unroll
        for (int s = 0; s < 32; s++)
            if (v[s] > best) { best = v[s]; bs = s; }
        int bj = bs * 32 + lane;
        #pragma unroll
        for (int off = 16; off; off >>= 1) {
            float ov = __shfl_xor_sync(0xffffffffu, best, off);
            int oj = __shfl_xor_sync(0xffffffffu, bj, off);
            if (ov > best || (ov == best && oj < bj)) { best = ov; bj = oj; }
        }
        if (lane == 0) idx[row * KNN + t] = bj;
        if ((bj & 31) == lane) {
            int ks = bj >> 5;
            #pragma unroll
            for (int s = 0; s < 32; s++)
                if (s == ks) v[s] = -FLT_MAX;
        }
    }
}

// =================== edge aggregate ===================
__global__ void aggregate_kernel(const float* __restrict__ ab, int O,
                                 const float* __restrict__ bias,
                                 const int* __restrict__ idx,
                                 float* __restrict__ out, int ldo, int ooff)
{
    int bi = blockIdx.x;
    int b = bi >> 10, i = bi & 1023;
    __shared__ int sj[KNN];
    if (threadIdx.x < KNN) sj[threadIdx.x] = idx[bi * KNN + threadIdx.x];
    __syncthreads();
    const float* abb = ab + (size_t)b * NP * 2 * O;
    for (int o = threadIdx.x; o < O; o += blockDim.x) {
        float a = abb[(size_t)i * 2 * O + o] + bias[o];
        float acc = 0.f;
        #pragma unroll
        for (int k = 0; k < KNN; k++) {
            float val = a + abb[(size_t)sj[k] * 2 * O + O + o];
            acc += fmaxf(val, 0.2f * val);
        }
        out[((size_t)b * NP + i) * ldo + ooff + o] = acc * 0.05f;
    }
}

// =================== pooling + final linear ===================
__global__ void pool_kernel(const float* __restrict__ hf, float* __restrict__ pooled)
{
    int b = blockIdx.x;
    int o = blockIdx.y * blockDim.x + threadIdx.x;
    float s = 0.f;
    for (int i = 0; i < NP; i++) s += hf[((size_t)b * NP + i) * 512 + o];
    pooled[b * 512 + o] = s * (1.f / NP);
}

__global__ void final_kernel(const float* __restrict__ pooled, const float* __restrict__ We,
                             float* __restrict__ out)
{
    int b = blockIdx.x, e = threadIdx.x;
    const float* p = pooled + b * 512;
    const float* w = We + e * 512;
    float s = 0.f;
    for (int o = 0; o < 512; o++) s += p[o] * w[o];
    out[b * 256 + e] = s;
}

// =================== host side ===================
struct LayerCfg { int C, O, coff; const float *W, *g, *be, *m, *v; };

extern "C" void kernel_launch(void* const* d_in, const int* in_sizes, int n_in,
                              void* d_out, int out_size)
{
    const float* x  = (const float*)d_in[0];
    const float* We = (const float*)d_in[21];

    float *dist, *xx, *cat, *ab, *hf, *pooled, *bias4;
    int* idx;
    __nv_bfloat16 *s1, *s2, *wabs4;
    cudaGetSymbolAddress((void**)&dist,   g_dist);
    cudaGetSymbolAddress((void**)&idx,    g_idx);
    cudaGetSymbolAddress((void**)&xx,     g_xx);
    cudaGetSymbolAddress((void**)&cat,    g_cat);
    cudaGetSymbolAddress((void**)&ab,     g_ab);
    cudaGetSymbolAddress((void**)&hf,     g_hf);
    cudaGetSymbolAddress((void**)&pooled, g_pooled);
    cudaGetSymbolAddress((void**)&bias4,  g_bias4);
    cudaGetSymbolAddress((void**)&s1,     g_s1);
    cudaGetSymbolAddress((void**)&s2,     g_s2);
    cudaGetSymbolAddress((void**)&wabs4,  g_wabs4);

    static cudaStream_t sB = nullptr;
    static cudaEvent_t evRoot, evS[4], evB[4];
    static bool attrSet = false;
    if (!sB) {
        cudaStreamCreateWithFlags(&sB, cudaStreamNonBlocking);
        cudaEventCreateWithFlags(&evRoot, cudaEventDisableTiming);
        for (int i = 0; i < 4; i++) {
            cudaEventCreateWithFlags(&evS[i], cudaEventDisableTiming);
            cudaEventCreateWithFlags(&evB[i], cudaEventDisableTiming);
        }
    }
    if (!attrSet) {
        cudaFuncSetAttribute(mma_gemm_kernel,
                             cudaFuncAttributeMaxDynamicSharedMemorySize, GEMM_SMEM);
        attrSet = true;
    }

    LayerCfg L[4] = {
        {  3,  64,   0, (const float*)d_in[1],  (const float*)d_in[2],  (const float*)d_in[3],  (const float*)d_in[4],  (const float*)d_in[5]  },
        { 64, 128,   0, (const float*)d_in[6],  (const float*)d_in[7],  (const float*)d_in[8],  (const float*)d_in[9],  (const float*)d_in[10] },
        {128, 256,  64, (const float*)d_in[11], (const float*)d_in[12], (const float*)d_in[13], (const float*)d_in[14], (const float*)d_in[15] },
        {448, 512,   0, (const float*)d_in[16], (const float*)d_in[17], (const float*)d_in[18], (const float*)d_in[19], (const float*)d_in[20] },
    };
    int ooffs[4] = {0, 64, 192, 0};

    // fork second stream into the capture
    cudaEventRecord(evRoot, 0);
    cudaStreamWaitEvent(sB, evRoot, 0);

    // all weight folds up-front on stream B (depend only on weights)
    for (int i = 0; i < 4; i++) {
        int Kp = ((3 * L[i].C + 63) / 64) * 64;
        wfoldsplit_kernel<<<2 * L[i].O, 128, 0, sB>>>(
            L[i].W, L[i].g, L[i].be, L[i].m, L[i].v, L[i].O, L[i].C, Kp,
            wabs4 + (size_t)i * 1024 * KPMAX, bias4 + i * 512);
    }

    for (int i = 0; i < 4; i++) {
        int C = L[i].C, O = L[i].O, coff = L[i].coff;
        int Kp = ((3 * C + 63) / 64) * 64;
        const float* hin = (i == 0) ? x : cat;
        int ld = (i == 0) ? 3 : 448;
        float* outbuf = (i == 3) ? hf : cat;
        int ldo = (i == 3) ? 512 : 448;

        // main: feature split
        split_kernel<<<NB * NP, 128>>>(hin, ld, coff, C, (long long)NP * ld, NP,
                                       s1, s2, Kp, xx);
        cudaEventRecord(evS[i], 0);

        // stream B: weight GEMM (needs split + wfold)
        cudaStreamWaitEvent(sB, evS[i], 0);
        dim3 gw((2 * O) / 128, NP / 128, NB);
        mma_gemm_kernel<<<gw, 256, GEMM_SMEM, sB>>>(
            s1, wabs4 + (size_t)i * 1024 * KPMAX, Kp,
            (long long)NP * Kp, 0, nullptr, 1, ab, 2 * O);
        cudaEventRecord(evB[i], sB);

        // main: dist GEMM + topk (independent of weight GEMM)
        dim3 gd(NP / 128, NP / 128, NB);
        mma_gemm_kernel<<<gd, 256, GEMM_SMEM>>>(
            s1, s2, Kp, (long long)NP * Kp, (long long)NP * Kp,
            xx, 0, dist, NP);
        topk_kernel<<<NB * NP / 8, 256>>>(dist, idx);

        // join: aggregate needs idx + ab
        cudaStreamWaitEvent(0, evB[i], 0);
        int bt = O < 256 ? O : 256;
        aggregate_kernel<<<NB * NP, bt>>>(ab, O, bias4 + i * 512, idx,
                                          outbuf, ldo, ooffs[i]);
    }

    pool_kernel<<<dim3(NB, 2), 256>>>(hf, pooled);
    final_kernel<<<NB, 256>>>(pooled, We, (float*)d_out);
}